// round 9
// baseline (speedup 1.0000x reference)
#include <cuda_runtime.h>
#include <cuda_bf16.h>
#include <cstdint>
#include <math.h>

#define NB   2048
#define KS   8
#define HID  256
#define IMG_HW 16384

#define KENC 2560   // glimpse K padded (2500 real)
#define KREL 768    // rel K padded (718 real)
#define KTEM 3136   // tem K padded (3118 real)
#define NGATE 1024

// xrel col offsets: [enc100|zwl3|pzw3|zwhatl50|pzwhat50|hl256|h_r256]
#define XR_ZWL 100
#define XR_PZW 103
#define XR_ZWHATL 106
#define XR_PZWHAT 156
#define XR_HL  206
#define XR_HR  462
// xtem col offsets: [g2 2500|zw3|pzw3|zwhatl50|pzwhat50|hl256|h_r2 256]
#define XT_ZW 2500
#define XT_PZW 2503
#define XT_ZWHATL 2506
#define XT_PZWHAT 2556
#define XT_HL 2606
#define XT_HR 2862

// ---------------- scratch ----------------
// k-major layout: row = k*NB + n
__device__ __nv_bfloat16 d_G1h[(size_t)NB * KS * KENC];
__device__ __nv_bfloat16 d_G1l[(size_t)NB * KS * KENC];
__device__ __nv_bfloat16 d_xrh[(size_t)NB * KS * KREL];
__device__ __nv_bfloat16 d_xrl[(size_t)NB * KS * KREL];
__device__ __nv_bfloat16 d_xth[(size_t)NB * KTEM];
__device__ __nv_bfloat16 d_xtl[(size_t)NB * KTEM];
__device__ float d_hr[(size_t)NB * HID];
__device__ float d_cr[(size_t)NB * HID];
// weights: gate-interleaved rows (row' = unit*4 + gate)
__device__ __nv_bfloat16 d_Wrh[(size_t)NGATE * KREL];
__device__ __nv_bfloat16 d_Wrl[(size_t)NGATE * KREL];
__device__ __nv_bfloat16 d_Wth[(size_t)NGATE * KTEM];
__device__ __nv_bfloat16 d_Wtl[(size_t)NGATE * KTEM];
__device__ __nv_bfloat16 d_Wgh[(size_t)128 * KENC];
__device__ __nv_bfloat16 d_Wgl[(size_t)128 * KENC];
__device__ float d_brel[NGATE];
__device__ float d_btem[NGATE];

// ---------------- ptx helpers (sm_80-era, safe for compute_103 PTX) ----------------
__device__ __forceinline__ uint32_t smem_u32(const void* p) {
    uint32_t a;
    asm("{ .reg .u64 t; cvta.to.shared.u64 t, %1; cvt.u32.u64 %0, t; }" : "=r"(a) : "l"(p));
    return a;
}
__device__ __forceinline__ void cp16(uint32_t dst, const void* src) {
    asm volatile("cp.async.ca.shared.global [%0], [%1], 16;" :: "r"(dst), "l"(src));
}
__device__ __forceinline__ void cp_commit() { asm volatile("cp.async.commit_group;"); }
__device__ __forceinline__ void cp_wait2() { asm volatile("cp.async.wait_group 2;"); }
__device__ __forceinline__ void cp_wait1() { asm volatile("cp.async.wait_group 1;"); }
__device__ __forceinline__ void cp_wait0() { asm volatile("cp.async.wait_group 0;"); }
__device__ __forceinline__ void ldm_x4(uint32_t* r, uint32_t a) {
    asm volatile("ldmatrix.sync.aligned.m8n8.x4.shared.b16 {%0,%1,%2,%3}, [%4];"
                 : "=r"(r[0]), "=r"(r[1]), "=r"(r[2]), "=r"(r[3]) : "r"(a));
}
__device__ __forceinline__ void ldm_x2(uint32_t* r, uint32_t a) {
    asm volatile("ldmatrix.sync.aligned.m8n8.x2.shared.b16 {%0,%1}, [%2];"
                 : "=r"(r[0]), "=r"(r[1]) : "r"(a));
}
__device__ __forceinline__ void mma_bf16(float* c, const uint32_t* a, const uint32_t* b) {
    asm volatile("mma.sync.aligned.m16n8k16.row.col.f32.bf16.bf16.f32 "
                 "{%0,%1,%2,%3}, {%4,%5,%6,%7}, {%8,%9}, {%0,%1,%2,%3};"
                 : "+f"(c[0]), "+f"(c[1]), "+f"(c[2]), "+f"(c[3])
                 : "r"(a[0]), "r"(a[1]), "r"(a[2]), "r"(a[3]), "r"(b[0]), "r"(b[1]));
}

// ---------------- math helpers ----------------
__device__ __forceinline__ float sigm(float x) { return 1.0f / (1.0f + expf(-x)); }
__device__ __forceinline__ float warp_sum(float v) {
#pragma unroll
    for (int o = 16; o; o >>= 1) v += __shfl_xor_sync(0xffffffffu, v, o);
    return v;
}
__device__ __forceinline__ void wpair(__nv_bfloat16* ph, __nv_bfloat16* pl, int i, float x) {
    __nv_bfloat16 h = __float2bfloat16(x);
    ph[i] = h;
    pl[i] = __float2bfloat16(x - __bfloat162float(h));
}
__device__ __forceinline__ float samp(const float* __restrict__ im, int y, int x) {
    if ((unsigned)y < 128u && (unsigned)x < 128u) return im[(y << 7) + x];
    return 0.0f;
}
__device__ __forceinline__ void glimpse_pair(const float* __restrict__ imgN,
                                             float s, float tx, float ty,
                                             __nv_bfloat16* __restrict__ dh,
                                             __nv_bfloat16* __restrict__ dl, int t) {
    for (int g = t; g < 2500; g += 256) {
        int iy = g / 50, ix = g - iy * 50;
        float gx = -1.0f + (float)ix * (2.0f / 49.0f);
        float gy = -1.0f + (float)iy * (2.0f / 49.0f);
        float px = (s * gx + tx + 1.0f) * 0.5f * 127.0f;
        float py = (s * gy + ty + 1.0f) * 0.5f * 127.0f;
        float x0f = floorf(px), y0f = floorf(py);
        float wx1 = px - x0f, wy1 = py - y0f;
        int x0 = (int)x0f, y0 = (int)y0f;
        float v00 = samp(imgN, y0, x0),     v01 = samp(imgN, y0, x0 + 1);
        float v10 = samp(imgN, y0 + 1, x0), v11 = samp(imgN, y0 + 1, x0 + 1);
        float r = (1.0f - wy1) * (1.0f - wx1) * v00 + (1.0f - wy1) * wx1 * v01
                + wy1 * (1.0f - wx1) * v10 + wy1 * wx1 * v11;
        wpair(dh, dl, g, r);
    }
}

// ---------------- prep ----------------
__global__ void prep_kernel(const float* __restrict__ Wih_rel, const float* __restrict__ Whh_rel,
                            const float* __restrict__ bih_rel, const float* __restrict__ bhh_rel,
                            const float* __restrict__ Wih_tem, const float* __restrict__ Whh_tem,
                            const float* __restrict__ bih_tem, const float* __restrict__ bhh_tem,
                            const float* __restrict__ Wg) {
    int tid = blockIdx.x * blockDim.x + threadIdx.x;
    int nt = gridDim.x * blockDim.x;
    // gate-interleaved: out row r' -> unit u=r'>>2, gate g=r'&3, orig row = g*256+u
    for (int i = tid; i < NGATE * KREL; i += nt) {
        int rp = i / KREL, c = i - rp * KREL;
        int orig = (rp & 3) * 256 + (rp >> 2);
        float v = 0.0f;
        if (c < 462) v = Wih_rel[orig * 462 + c];
        else if (c < 718) v = Whh_rel[orig * 256 + (c - 462)];
        wpair(d_Wrh, d_Wrl, i, v);
    }
    for (int i = tid; i < NGATE * KTEM; i += nt) {
        int rp = i / KTEM, c = i - rp * KTEM;
        int orig = (rp & 3) * 256 + (rp >> 2);
        float v = 0.0f;
        if (c < 2862) v = Wih_tem[orig * 2862 + c];
        else if (c < 3118) v = Whh_tem[orig * 256 + (c - 2862)];
        wpair(d_Wth, d_Wtl, i, v);
    }
    for (int i = tid; i < 128 * KENC; i += nt) {
        int r = i / KENC, c = i - r * KENC;
        float v = (r < 100 && c < 2500) ? Wg[r * 2500 + c] : 0.0f;
        wpair(d_Wgh, d_Wgl, i, v);
    }
    for (int i = tid; i < NGATE; i += nt) {
        int orig = (i & 3) * 256 + (i >> 2);
        d_brel[i] = bih_rel[orig] + bhh_rel[orig];
        d_btem[i] = bih_tem[orig] + bhh_tem[orig];
    }
    for (int i = tid; i < NB * HID; i += nt) { d_hr[i] = 0.0f; d_cr[i] = 0.0f; }
    // zero recurrent xrel cols for k=0 rows (rows 0..NB-1)
    __nv_bfloat16 z = __float2bfloat16(0.0f);
    for (int i = tid; i < NB * 3; i += nt) {
        int r = i / 3, c = XR_PZW + i % 3;
        d_xrh[(size_t)r * KREL + c] = z; d_xrl[(size_t)r * KREL + c] = z;
    }
    for (int i = tid; i < NB * 50; i += nt) {
        int r = i / 50, c = XR_PZWHAT + i % 50;
        d_xrh[(size_t)r * KREL + c] = z; d_xrl[(size_t)r * KREL + c] = z;
    }
    for (int i = tid; i < NB * HID; i += nt) {
        int r = i / HID, c = XR_HR + i % HID;
        d_xrh[(size_t)r * KREL + c] = z; d_xrl[(size_t)r * KREL + c] = z;
    }
    // pads
    for (int i = tid; i < NB * KS * 60; i += nt) {
        int r = i / 60, c = 2500 + i % 60;
        d_G1h[(size_t)r * KENC + c] = z; d_G1l[(size_t)r * KENC + c] = z;
    }
    for (int i = tid; i < NB * KS * 50; i += nt) {
        int r = i / 50, c = 718 + i % 50;
        d_xrh[(size_t)r * KREL + c] = z; d_xrl[(size_t)r * KREL + c] = z;
    }
    for (int i = tid; i < NB * 18; i += nt) {
        int r = i / 18, c = 3118 + i % 18;
        d_xth[(size_t)r * KTEM + c] = z; d_xtl[(size_t)r * KTEM + c] = z;
    }
}

// ---------------- static pack: zwb + glimpse1 + static xrel cols, all (n,k) ----------------
__global__ __launch_bounds__(256) void staticpack_kernel(
    const float* __restrict__ img, const float* __restrict__ hidden_last,
    const float* __restrict__ zwhere_last, const float* __restrict__ zwhat_last,
    const float* __restrict__ W_loca, const float* __restrict__ b_loca) {
    int row = blockIdx.x, t = threadIdx.x;   // row = k*NB + n
    int k = row / NB, n = row - k * NB;
    size_t inrow = (size_t)n * KS + k;
    __shared__ float sred[3][8];
    __shared__ float szw[3];
    int w = t >> 5, lane = t & 31;

    float h = hidden_last[inrow * HID + t];
    float p0 = h * W_loca[t];
    float p1 = h * W_loca[HID + t];
    float p2 = h * W_loca[2 * HID + t];
    p0 = warp_sum(p0); p1 = warp_sum(p1); p2 = warp_sum(p2);
    if (lane == 0) { sred[0][w] = p0; sred[1][w] = p1; sred[2][w] = p2; }

    __nv_bfloat16* xh = d_xrh + (size_t)row * KREL;
    __nv_bfloat16* xl = d_xrl + (size_t)row * KREL;
    wpair(xh, xl, XR_HL + t, h);
    if (t < 3)  wpair(xh, xl, XR_ZWL + t, zwhere_last[inrow * 3 + t]);
    if (t < 50) wpair(xh, xl, XR_ZWHATL + t, zwhat_last[inrow * 50 + t]);
    __syncthreads();
    if (t < 3) {
        float s = 0.0f;
#pragma unroll
        for (int q = 0; q < 8; q++) s += sred[t][q];
        s += b_loca[t];
        szw[t] = fmaxf(s, 0.0f) + zwhere_last[inrow * 3 + t];
    }
    __syncthreads();
    glimpse_pair(img + (size_t)n * IMG_HW, szw[0], szw[1], szw[2],
                 d_G1h + (size_t)row * KENC, d_G1l + (size_t)row * KENC, t);
}

// ---------------- HMMA split-bf16 GEMM, fused epilogues ----------------
// CTA 64x128 (MxN), BK=32, 3-stage cp.async, 2 CTAs/SM.
// smem rows stride 80B (gcd(5,8)=1 -> ldmatrix conflict-free).
// Stage layout: Ah(64r) | Al(64r) | Bh(128r) | Bl(128r)  = 384 rows * 80B = 30720B
// EPI 0: rel LSTM pointwise (write d_cr, d_hr)
// EPI 1: relu -> (hi,lo) bf16 out (enc)
// EPI 2: tem LSTM pointwise (read d_cr, write htemp_out)
#define ROW_B 80
#define OFF_AL (64 * ROW_B)          // 5120
#define OFF_BH (128 * ROW_B)         // 10240
#define OFF_BL (256 * ROW_B)         // 20480
#define STAGE_B (384 * ROW_B)        // 30720
#define SMEM_REQ (3 * STAGE_B)       // 92160

template <int EPI>
__global__ __launch_bounds__(256, 2) void hmma_gemm(
    const __nv_bfloat16* __restrict__ Ah, const __nv_bfloat16* __restrict__ Al, int lda,
    const __nv_bfloat16* __restrict__ Bh, const __nv_bfloat16* __restrict__ Bl, int ldb,
    const float* __restrict__ bias,
    float* __restrict__ cstate, float* __restrict__ hout,
    __nv_bfloat16* __restrict__ Chi, __nv_bfloat16* __restrict__ Clo,
    int ldc, int K, int nReal, int kk) {
    extern __shared__ char smem[];
    const uint32_t sb = smem_u32(smem);
    const int tid = threadIdx.x;
    const int lane = tid & 31, wid = tid >> 5;
    const int wm = wid >> 2, wn = wid & 3;      // 2 x 4 warp grid; warp tile 32x32
    const int bm = blockIdx.y * 64, bn = blockIdx.x * 128;
    const int nK = K / 32;

    float acc[2][4][4];
#pragma unroll
    for (int i = 0; i < 2; i++)
#pragma unroll
        for (int j = 0; j < 4; j++)
#pragma unroll
            for (int q = 0; q < 4; q++) acc[i][j][q] = 0.0f;

    auto load_stage = [&](int st, int kt) {
        int k0 = kt * 32;
        uint32_t base = sb + st * STAGE_B;
        // 384 rows * 4 chunks of 16B = 1536 cp.async ops; 256 threads -> 6 each
#pragma unroll
        for (int q = 0; q < 6; q++) {
            int idx = q * 256 + tid;          // 0..1535
            int row = idx >> 2;               // 0..383
            int ch = idx & 3;                 // 0..3
            const __nv_bfloat16* gp;
            if (row < 64)       gp = Ah + (size_t)(bm + row) * lda + k0 + ch * 8;
            else if (row < 128) gp = Al + (size_t)(bm + row - 64) * lda + k0 + ch * 8;
            else if (row < 256) gp = Bh + (size_t)(bn + row - 128) * ldb + k0 + ch * 8;
            else                gp = Bl + (size_t)(bn + row - 256) * ldb + k0 + ch * 8;
            cp16(base + row * ROW_B + ch * 16, gp);
        }
        cp_commit();
    };

    load_stage(0, 0);
    load_stage(1, 1);
    int st = 0;
    for (int kt = 0; kt < nK; kt++) {
        if (kt + 2 < nK) { load_stage((kt + 2) % 3, kt + 2); cp_wait2(); }
        else if (kt + 1 < nK) cp_wait1();
        else cp_wait0();
        __syncthreads();
        uint32_t base = sb + st * STAGE_B;
        st = (st + 1 == 3) ? 0 : st + 1;
#pragma unroll
        for (int ks = 0; ks < 2; ks++) {
            uint32_t ah[2][4], al[2][4], bh[4][2], bl[4][2];
#pragma unroll
            for (int mf = 0; mf < 2; mf++) {
                int row = wm * 32 + mf * 16 + (lane & 15);
                int ch = ks * 2 + (lane >> 4);
                uint32_t a = base + row * ROW_B + ch * 16;
                ldm_x4(ah[mf], a);
                ldm_x4(al[mf], a + OFF_AL);
            }
#pragma unroll
            for (int nf = 0; nf < 4; nf++) {
                int row = wn * 32 + nf * 8 + (lane & 7);
                int ch = ks * 2 + ((lane >> 3) & 1);
                uint32_t a = base + OFF_BH + row * ROW_B + ch * 16;
                ldm_x2(bh[nf], a);
                ldm_x2(bl[nf], a + (OFF_BL - OFF_BH));
            }
#pragma unroll
            for (int mf = 0; mf < 2; mf++)
#pragma unroll
                for (int nf = 0; nf < 4; nf++) {
                    mma_bf16(acc[mf][nf], ah[mf], bh[nf]);
                    mma_bf16(acc[mf][nf], al[mf], bh[nf]);
                    mma_bf16(acc[mf][nf], ah[mf], bl[nf]);
                }
        }
        __syncthreads();
    }

    // epilogue
    int trow = lane >> 2, tcol2 = (lane & 3) * 2;
    bool evn = ((lane & 1) == 0);   // holds (i,f); odd holds (g,o)
#pragma unroll
    for (int mf = 0; mf < 2; mf++) {
        int r0 = bm + wm * 32 + mf * 16 + trow;
#pragma unroll
        for (int nf = 0; nf < 4; nf++) {
            int col = bn + wn * 32 + nf * 8 + tcol2;
            if (EPI == 1) {
#pragma unroll
                for (int e = 0; e < 4; e++) {
                    int cc = col + (e & 1);
                    int rr = r0 + (e >> 1) * 8;
                    if (cc < nReal) {
                        float v = fmaxf(acc[mf][nf][e] + bias[cc], 0.0f);
                        wpair(Chi + (size_t)rr * ldc, Clo + (size_t)rr * ldc, cc, v);
                    }
                }
            } else {
                int u = col >> 2;  // hidden unit
                float b0 = bias[col], b1 = bias[col + 1];
                float x0 = acc[mf][nf][0] + b0, x1 = acc[mf][nf][1] + b1;
                float x2 = acc[mf][nf][2] + b0, x3 = acc[mf][nf][3] + b1;
                float vA0, vB0, vA1, vB1;
                if (evn) { vA0 = sigm(x0); vB0 = sigm(x1); vA1 = sigm(x2); vB1 = sigm(x3); }
                else     { vA0 = tanhf(x0); vB0 = sigm(x1); vA1 = tanhf(x2); vB1 = sigm(x3); }
                // exchange: even receives tanh(g); odd receives sigm(i) (unused)
                float tA0 = __shfl_xor_sync(0xffffffffu, vA0, 1);
                float tA1 = __shfl_xor_sync(0xffffffffu, vA1, 1);
                float c20 = 0.0f, c21 = 0.0f;
                if (evn) {
                    float co0 = cstate[(size_t)r0 * HID + u];
                    float co1 = cstate[(size_t)(r0 + 8) * HID + u];
                    c20 = vB0 * co0 + vA0 * tA0;
                    c21 = vB1 * co1 + vA1 * tA1;
                    if (EPI == 0) {
                        cstate[(size_t)r0 * HID + u] = c20;
                        cstate[(size_t)(r0 + 8) * HID + u] = c21;
                    }
                }
                float cr0 = __shfl_xor_sync(0xffffffffu, c20, 1);
                float cr1 = __shfl_xor_sync(0xffffffffu, c21, 1);
                if (!evn) {
                    float h0 = vB0 * tanhf(cr0);
                    float h1 = vB1 * tanhf(cr1);
                    if (EPI == 0) {
                        hout[(size_t)r0 * HID + u] = h0;
                        hout[(size_t)(r0 + 8) * HID + u] = h1;
                    } else {   // EPI == 2: write h_t to output [n, k, HID]
                        hout[((size_t)r0 * KS + kk) * HID + u] = h0;
                        hout[((size_t)(r0 + 8) * KS + kk) * HID + u] = h1;
                    }
                }
            }
        }
    }
}

// ---------------- rel stage 2: zw linear + glimpse2 + xtem pack ----------------
__global__ __launch_bounds__(256) void relglimpse2_kernel(
    const float* __restrict__ img, const float* __restrict__ hidden_last,
    const float* __restrict__ zwhere_last, const float* __restrict__ zwhat_last,
    const float* __restrict__ Wm_wh, const float* __restrict__ bm_wh,
    const float* __restrict__ zwhat_out, float* __restrict__ zwhere_out, int k) {
    int n = blockIdx.x, t = threadIdx.x;
    __shared__ float hs[HID];
    __shared__ float sred[3][8];
    __shared__ float szw[3];
    int w = t >> 5, lane = t & 31;

    float h = d_hr[n * HID + t];    // h_r2 from rel GEMM epilogue
    hs[t] = h;

    __nv_bfloat16* xh = d_xth + (size_t)n * KTEM;
    __nv_bfloat16* xl = d_xtl + (size_t)n * KTEM;
    wpair(xh, xl, XT_HR + t, h);
    wpair(xh, xl, XT_HL + t, hidden_last[((size_t)n * KS + k) * HID + t]);
    if (t < 3) wpair(xh, xl, XT_PZW + t, k ? zwhere_out[((size_t)n * KS + k - 1) * 3 + t] : 0.0f);
    if (t < 50) {
        wpair(xh, xl, XT_ZWHATL + t, zwhat_last[((size_t)n * KS + k) * 50 + t]);
        wpair(xh, xl, XT_PZWHAT + t, k ? zwhat_out[((size_t)n * KS + k - 1) * 50 + t] : 0.0f);
    }
    __syncthreads();

    // zw = [zwl(3), h_r2(256)] @ Wm_wh^T + bm_wh (K=259)
    float c0 = (t < 3) ? zwhere_last[((size_t)n * KS + k) * 3 + t] : hs[t - 3];
    float q0 = c0 * Wm_wh[t];
    float q1 = c0 * Wm_wh[259 + t];
    float q2 = c0 * Wm_wh[518 + t];
    if (t < 3) {
        float c1 = hs[253 + t];
        q0 += c1 * Wm_wh[256 + t];
        q1 += c1 * Wm_wh[259 + 256 + t];
        q2 += c1 * Wm_wh[518 + 256 + t];
    }
    q0 = warp_sum(q0); q1 = warp_sum(q1); q2 = warp_sum(q2);
    if (lane == 0) { sred[0][w] = q0; sred[1][w] = q1; sred[2][w] = q2; }
    __syncthreads();
    if (t < 3) {
        float s = 0.0f;
#pragma unroll
        for (int q = 0; q < 8; q++) s += sred[t][q];
        s += bm_wh[t];
        szw[t] = s;
        zwhere_out[((size_t)n * KS + k) * 3 + t] = s;
        wpair(xh, xl, XT_ZW + t, s);
    }
    __syncthreads();
    glimpse_pair(img + (size_t)n * IMG_HW, szw[0], szw[1], szw[2], xh, xl, t);
}

// ---------------- head: zwhat GEMV + presence + fused recpack for step k+1 ----------------
__global__ __launch_bounds__(256) void head_kernel(
    const float* __restrict__ zwhat_last, const float* __restrict__ zpres_last,
    const float* __restrict__ Wm_wt, const float* __restrict__ bm_wt,
    const float* __restrict__ Wm_pr, const float* __restrict__ bm_pr,
    const float* __restrict__ Ws_pr, const float* __restrict__ bs_pr,
    const float* __restrict__ zwhere_out, float* __restrict__ zwhat_out,
    float* __restrict__ zpres_out, const float* __restrict__ htemp_out, int k) {
    int n = blockIdx.x, t = threadIdx.x;
    __shared__ float xs[562];
    __shared__ float ys[565];
    __shared__ float red[16];
    int w = t >> 5, lane = t & 31;

    float ht = htemp_out[((size_t)n * KS + k) * HID + t];  // from tem GEMM epilogue
    float hr = d_hr[n * HID + t];
    xs[50 + t] = hr; xs[306 + t] = ht;
    ys[53 + t] = hr; ys[309 + t] = ht;
    if (t < 50) xs[t] = zwhat_last[((size_t)n * KS + k) * 50 + t];
    if (t < 3) ys[50 + t] = zwhere_out[((size_t)n * KS + k) * 3 + t];
    __syncthreads();

    for (int j = w; j < 50; j += 8) {
        const float* wr = Wm_wt + (size_t)j * 562;
        float acc = 0.0f;
        for (int i = lane; i < 562; i += 32) acc += xs[i] * wr[i];
        acc = warp_sum(acc);
        if (lane == 0) {
            float z = acc + bm_wt[j];
            ys[j] = z;
            zwhat_out[((size_t)n * KS + k) * 50 + j] = z;
        }
    }
    __syncthreads();

    // fused recpack for step k+1 (k-major xrel rows (k+1)*NB + n)
    if (k < KS - 1) {
        size_t row = (size_t)(k + 1) * NB + n;
        __nv_bfloat16* xh = d_xrh + row * KREL;
        __nv_bfloat16* xl = d_xrl + row * KREL;
        wpair(xh, xl, XR_HR + t, hr);
        if (t < 3)  wpair(xh, xl, XR_PZW + t, ys[50 + t]);
        if (t < 50) wpair(xh, xl, XR_PZWHAT + t, ys[t]);
    }

    // presence: two 565-dots across the block
    float am = 0.0f, as = 0.0f;
    for (int i = t; i < 565; i += 256) {
        float x = ys[i];
        am += x * Wm_pr[i];
        as += x * Ws_pr[i];
    }
    am = warp_sum(am); as = warp_sum(as);
    if (lane == 0) { red[w] = am; red[8 + w] = as; }
    __syncthreads();
    if (t == 0) {
        float m = 0.0f, s = 0.0f;
#pragma unroll
        for (int q = 0; q < 8; q++) { m += red[q]; s += red[8 + q]; }
        float p = sigm(m + bm_pr[0]) * sigm(s + bs_pr[0]);
        zpres_out[(size_t)n * KS + k] = p * zpres_last[(size_t)n * KS + k];
    }
}

// ---------------- host ----------------
extern "C" void kernel_launch(void* const* d_in, const int* in_sizes, int n_in,
                              void* d_out, int out_size) {
    const float* img         = (const float*)d_in[0];
    const float* zwhat_last  = (const float*)d_in[1];
    const float* zwhere_last = (const float*)d_in[2];
    const float* zpres_last  = (const float*)d_in[3];
    const float* hidden_last = (const float*)d_in[4];
    const float* W_loca = (const float*)d_in[5];
    const float* b_loca = (const float*)d_in[6];
    const float* Wg     = (const float*)d_in[7];
    const float* bg     = (const float*)d_in[8];
    const float* Wih_rel = (const float*)d_in[9];
    const float* Whh_rel = (const float*)d_in[10];
    const float* bih_rel = (const float*)d_in[11];
    const float* bhh_rel = (const float*)d_in[12];
    const float* Wih_tem = (const float*)d_in[13];
    const float* Whh_tem = (const float*)d_in[14];
    const float* bih_tem = (const float*)d_in[15];
    const float* bhh_tem = (const float*)d_in[16];
    const float* Wm_wh = (const float*)d_in[17];
    const float* bm_wh = (const float*)d_in[18];
    const float* Wm_wt = (const float*)d_in[21];
    const float* bm_wt = (const float*)d_in[22];
    const float* Wm_pr = (const float*)d_in[25];
    const float* bm_pr = (const float*)d_in[26];
    const float* Ws_pr = (const float*)d_in[27];
    const float* bs_pr = (const float*)d_in[28];

    float* out = (float*)d_out;
    float* zwhat_out  = out;
    float* zwhere_out = out + (size_t)NB * KS * 50;
    float* zpres_out  = zwhere_out + (size_t)NB * KS * 3;
    float* htemp_out  = zpres_out + (size_t)NB * KS * 1;

    void *pG1h, *pG1l, *pXrh, *pXrl, *pXth, *pXtl;
    void *pWrh, *pWrl, *pWth, *pWtl, *pWgh, *pWgl, *pBrel, *pBtem, *pHr, *pCr;
    cudaGetSymbolAddress(&pG1h, d_G1h); cudaGetSymbolAddress(&pG1l, d_G1l);
    cudaGetSymbolAddress(&pXrh, d_xrh); cudaGetSymbolAddress(&pXrl, d_xrl);
    cudaGetSymbolAddress(&pXth, d_xth); cudaGetSymbolAddress(&pXtl, d_xtl);
    cudaGetSymbolAddress(&pWrh, d_Wrh); cudaGetSymbolAddress(&pWrl, d_Wrl);
    cudaGetSymbolAddress(&pWth, d_Wth); cudaGetSymbolAddress(&pWtl, d_Wtl);
    cudaGetSymbolAddress(&pWgh, d_Wgh); cudaGetSymbolAddress(&pWgl, d_Wgl);
    cudaGetSymbolAddress(&pBrel, d_brel); cudaGetSymbolAddress(&pBtem, d_btem);
    cudaGetSymbolAddress(&pHr, d_hr); cudaGetSymbolAddress(&pCr, d_cr);

    cudaFuncSetAttribute(hmma_gemm<0>, cudaFuncAttributeMaxDynamicSharedMemorySize, SMEM_REQ);
    cudaFuncSetAttribute(hmma_gemm<1>, cudaFuncAttributeMaxDynamicSharedMemorySize, SMEM_REQ);
    cudaFuncSetAttribute(hmma_gemm<2>, cudaFuncAttributeMaxDynamicSharedMemorySize, SMEM_REQ);

    prep_kernel<<<2048, 256>>>(Wih_rel, Whh_rel, bih_rel, bhh_rel,
                               Wih_tem, Whh_tem, bih_tem, bhh_tem, Wg);
    staticpack_kernel<<<NB * KS, 256>>>(img, hidden_last, zwhere_last, zwhat_last,
                                        W_loca, b_loca);
    // enc GEMM: M=16384, N=128(100 real), K=2560 -> xrel[:,0:100] hi/lo
    {
        dim3 grid(1, NB * KS / 64);
        hmma_gemm<1><<<grid, 256, SMEM_REQ>>>(
            (const __nv_bfloat16*)pG1h, (const __nv_bfloat16*)pG1l, KENC,
            (const __nv_bfloat16*)pWgh, (const __nv_bfloat16*)pWgl, KENC,
            bg, nullptr, nullptr,
            (__nv_bfloat16*)pXrh, (__nv_bfloat16*)pXrl, KREL,
            KENC, 100, 0);
    }
    for (int k = 0; k < KS; k++) {
        // rel gates GEMM + LSTM epilogue: M=2048 (k-major rows), N=1024, K=768
        {
            dim3 grid(NGATE / 128, NB / 64);
            hmma_gemm<0><<<grid, 256, SMEM_REQ>>>(
                (const __nv_bfloat16*)pXrh + (size_t)k * NB * KREL,
                (const __nv_bfloat16*)pXrl + (size_t)k * NB * KREL, KREL,
                (const __nv_bfloat16*)pWrh, (const __nv_bfloat16*)pWrl, KREL,
                (const float*)pBrel, (float*)pCr, (float*)pHr,
                nullptr, nullptr, 0, KREL, NGATE, k);
        }
        relglimpse2_kernel<<<NB, 256>>>(img, hidden_last, zwhere_last, zwhat_last,
                                        Wm_wh, bm_wh, zwhat_out, zwhere_out, k);
        // tem gates GEMM + LSTM epilogue (writes htemp_out): M=2048, N=1024, K=3136
        {
            dim3 grid(NGATE / 128, NB / 64);
            hmma_gemm<2><<<grid, 256, SMEM_REQ>>>(
                (const __nv_bfloat16*)pXth, (const __nv_bfloat16*)pXtl, KTEM,
                (const __nv_bfloat16*)pWth, (const __nv_bfloat16*)pWtl, KTEM,
                (const float*)pBtem, (float*)pCr, htemp_out,
                nullptr, nullptr, 0, KTEM, NGATE, k);
        }
        head_kernel<<<NB, 256>>>(zwhat_last, zpres_last, Wm_wt, bm_wt,
                                 Wm_pr, bm_pr, Ws_pr, bs_pr,
                                 zwhere_out, zwhat_out, zpres_out, htemp_out, k);
    }
}

// round 10
// speedup vs baseline: 1.3289x; 1.3289x over previous
#include <cuda_runtime.h>
#include <cuda_fp16.h>
#include <cstdint>
#include <math.h>

#define NB   2048
#define KS   8
#define HID  256
#define IMG_HW 16384

#define KENC 2560   // glimpse K padded (2500 real)
#define KREL 768    // rel K padded (718 real)
#define KTEM 3136   // tem K padded (3118 real)
#define NGATE 1024

// xrel col offsets: [enc100|zwl3|pzw3|zwhatl50|pzwhat50|hl256|h_r256]
#define XR_ZWL 100
#define XR_PZW 103
#define XR_ZWHATL 106
#define XR_PZWHAT 156
#define XR_HL  206
#define XR_HR  462
// xtem col offsets: [g2 2500|zw3|pzw3|zwhatl50|pzwhat50|hl256|h_r2 256]
#define XT_ZW 2500
#define XT_PZW 2503
#define XT_ZWHATL 2506
#define XT_PZWHAT 2556
#define XT_HL 2606
#define XT_HR 2862

// ---------------- scratch ----------------
// activations as fp16 (hi, lo) pairs; k-major layout: row = k*NB + n
__device__ __half d_G1h[(size_t)NB * KS * KENC];
__device__ __half d_G1l[(size_t)NB * KS * KENC];
__device__ __half d_xrh[(size_t)NB * KS * KREL];
__device__ __half d_xrl[(size_t)NB * KS * KREL];
__device__ __half d_xth[(size_t)NB * KTEM];
__device__ __half d_xtl[(size_t)NB * KTEM];
__device__ float d_hr[(size_t)NB * HID];
__device__ float d_cr[(size_t)NB * HID];
// weights: single fp16, gate-interleaved rows (row' = unit*4 + gate)
__device__ __half d_Wr[(size_t)NGATE * KREL];
__device__ __half d_Wt[(size_t)NGATE * KTEM];
__device__ __half d_Wg[(size_t)128 * KENC];
__device__ float d_brel[NGATE];
__device__ float d_btem[NGATE];

// ---------------- ptx helpers (sm_80-era, safe for compute_103 PTX) ----------------
__device__ __forceinline__ uint32_t smem_u32(const void* p) {
    uint32_t a;
    asm("{ .reg .u64 t; cvta.to.shared.u64 t, %1; cvt.u32.u64 %0, t; }" : "=r"(a) : "l"(p));
    return a;
}
__device__ __forceinline__ void cp16(uint32_t dst, const void* src) {
    asm volatile("cp.async.ca.shared.global [%0], [%1], 16;" :: "r"(dst), "l"(src));
}
__device__ __forceinline__ void cp_commit() { asm volatile("cp.async.commit_group;"); }
__device__ __forceinline__ void cp_wait3() { asm volatile("cp.async.wait_group 3;"); }
__device__ __forceinline__ void cp_wait2() { asm volatile("cp.async.wait_group 2;"); }
__device__ __forceinline__ void cp_wait1() { asm volatile("cp.async.wait_group 1;"); }
__device__ __forceinline__ void cp_wait0() { asm volatile("cp.async.wait_group 0;"); }
__device__ __forceinline__ void ldm_x4(uint32_t* r, uint32_t a) {
    asm volatile("ldmatrix.sync.aligned.m8n8.x4.shared.b16 {%0,%1,%2,%3}, [%4];"
                 : "=r"(r[0]), "=r"(r[1]), "=r"(r[2]), "=r"(r[3]) : "r"(a));
}
__device__ __forceinline__ void ldm_x2(uint32_t* r, uint32_t a) {
    asm volatile("ldmatrix.sync.aligned.m8n8.x2.shared.b16 {%0,%1}, [%2];"
                 : "=r"(r[0]), "=r"(r[1]) : "r"(a));
}
__device__ __forceinline__ void mma_f16(float* c, const uint32_t* a, const uint32_t* b) {
    asm volatile("mma.sync.aligned.m16n8k16.row.col.f32.f16.f16.f32 "
                 "{%0,%1,%2,%3}, {%4,%5,%6,%7}, {%8,%9}, {%0,%1,%2,%3};"
                 : "+f"(c[0]), "+f"(c[1]), "+f"(c[2]), "+f"(c[3])
                 : "r"(a[0]), "r"(a[1]), "r"(a[2]), "r"(a[3]), "r"(b[0]), "r"(b[1]));
}

// ---------------- math helpers ----------------
__device__ __forceinline__ float sigm(float x) { return 1.0f / (1.0f + expf(-x)); }
__device__ __forceinline__ float warp_sum(float v) {
#pragma unroll
    for (int o = 16; o; o >>= 1) v += __shfl_xor_sync(0xffffffffu, v, o);
    return v;
}
// split fp32 -> fp16 hi + fp16 lo
__device__ __forceinline__ void wpair(__half* ph, __half* pl, int i, float x) {
    __half h = __float2half(x);
    ph[i] = h;
    pl[i] = __float2half(x - __half2float(h));
}
__device__ __forceinline__ float samp(const float* __restrict__ im, int y, int x) {
    if ((unsigned)y < 128u && (unsigned)x < 128u) return im[(y << 7) + x];
    return 0.0f;
}
__device__ __forceinline__ void glimpse_pair(const float* __restrict__ imgN,
                                             float s, float tx, float ty,
                                             __half* __restrict__ dh,
                                             __half* __restrict__ dl, int t) {
    for (int g = t; g < 2500; g += 256) {
        int iy = g / 50, ix = g - iy * 50;
        float gx = -1.0f + (float)ix * (2.0f / 49.0f);
        float gy = -1.0f + (float)iy * (2.0f / 49.0f);
        float px = (s * gx + tx + 1.0f) * 0.5f * 127.0f;
        float py = (s * gy + ty + 1.0f) * 0.5f * 127.0f;
        float x0f = floorf(px), y0f = floorf(py);
        float wx1 = px - x0f, wy1 = py - y0f;
        int x0 = (int)x0f, y0 = (int)y0f;
        float v00 = samp(imgN, y0, x0),     v01 = samp(imgN, y0, x0 + 1);
        float v10 = samp(imgN, y0 + 1, x0), v11 = samp(imgN, y0 + 1, x0 + 1);
        float r = (1.0f - wy1) * (1.0f - wx1) * v00 + (1.0f - wy1) * wx1 * v01
                + wy1 * (1.0f - wx1) * v10 + wy1 * wx1 * v11;
        wpair(dh, dl, g, r);
    }
}

// ---------------- prep ----------------
__global__ void prep_kernel(const float* __restrict__ Wih_rel, const float* __restrict__ Whh_rel,
                            const float* __restrict__ bih_rel, const float* __restrict__ bhh_rel,
                            const float* __restrict__ Wih_tem, const float* __restrict__ Whh_tem,
                            const float* __restrict__ bih_tem, const float* __restrict__ bhh_tem,
                            const float* __restrict__ Wg) {
    int tid = blockIdx.x * blockDim.x + threadIdx.x;
    int nt = gridDim.x * blockDim.x;
    // gate-interleaved: out row r' -> unit u=r'>>2, gate g=r'&3, orig row = g*256+u
    for (int i = tid; i < NGATE * KREL; i += nt) {
        int rp = i / KREL, c = i - rp * KREL;
        int orig = (rp & 3) * 256 + (rp >> 2);
        float v = 0.0f;
        if (c < 462) v = Wih_rel[orig * 462 + c];
        else if (c < 718) v = Whh_rel[orig * 256 + (c - 462)];
        d_Wr[i] = __float2half(v);
    }
    for (int i = tid; i < NGATE * KTEM; i += nt) {
        int rp = i / KTEM, c = i - rp * KTEM;
        int orig = (rp & 3) * 256 + (rp >> 2);
        float v = 0.0f;
        if (c < 2862) v = Wih_tem[orig * 2862 + c];
        else if (c < 3118) v = Whh_tem[orig * 256 + (c - 2862)];
        d_Wt[i] = __float2half(v);
    }
    for (int i = tid; i < 128 * KENC; i += nt) {
        int r = i / KENC, c = i - r * KENC;
        float v = (r < 100 && c < 2500) ? Wg[r * 2500 + c] : 0.0f;
        d_Wg[i] = __float2half(v);
    }
    for (int i = tid; i < NGATE; i += nt) {
        int orig = (i & 3) * 256 + (i >> 2);
        d_brel[i] = bih_rel[orig] + bhh_rel[orig];
        d_btem[i] = bih_tem[orig] + bhh_tem[orig];
    }
    for (int i = tid; i < NB * HID; i += nt) { d_hr[i] = 0.0f; d_cr[i] = 0.0f; }
    // zero recurrent xrel cols for k=0 rows (rows 0..NB-1)
    __half z = __float2half(0.0f);
    for (int i = tid; i < NB * 3; i += nt) {
        int r = i / 3, c = XR_PZW + i % 3;
        d_xrh[(size_t)r * KREL + c] = z; d_xrl[(size_t)r * KREL + c] = z;
    }
    for (int i = tid; i < NB * 50; i += nt) {
        int r = i / 50, c = XR_PZWHAT + i % 50;
        d_xrh[(size_t)r * KREL + c] = z; d_xrl[(size_t)r * KREL + c] = z;
    }
    for (int i = tid; i < NB * HID; i += nt) {
        int r = i / HID, c = XR_HR + i % HID;
        d_xrh[(size_t)r * KREL + c] = z; d_xrl[(size_t)r * KREL + c] = z;
    }
    // pads
    for (int i = tid; i < NB * KS * 60; i += nt) {
        int r = i / 60, c = 2500 + i % 60;
        d_G1h[(size_t)r * KENC + c] = z; d_G1l[(size_t)r * KENC + c] = z;
    }
    for (int i = tid; i < NB * KS * 50; i += nt) {
        int r = i / 50, c = 718 + i % 50;
        d_xrh[(size_t)r * KREL + c] = z; d_xrl[(size_t)r * KREL + c] = z;
    }
    for (int i = tid; i < NB * 18; i += nt) {
        int r = i / 18, c = 3118 + i % 18;
        d_xth[(size_t)r * KTEM + c] = z; d_xtl[(size_t)r * KTEM + c] = z;
    }
}

// ---------------- static pack: zwb + glimpse1 + static xrel cols, all (n,k) ----------------
__global__ __launch_bounds__(256) void staticpack_kernel(
    const float* __restrict__ img, const float* __restrict__ hidden_last,
    const float* __restrict__ zwhere_last, const float* __restrict__ zwhat_last,
    const float* __restrict__ W_loca, const float* __restrict__ b_loca) {
    int row = blockIdx.x, t = threadIdx.x;   // row = k*NB + n
    int k = row / NB, n = row - k * NB;
    size_t inrow = (size_t)n * KS + k;
    __shared__ float sred[3][8];
    __shared__ float szw[3];
    int w = t >> 5, lane = t & 31;

    float h = hidden_last[inrow * HID + t];
    float p0 = h * W_loca[t];
    float p1 = h * W_loca[HID + t];
    float p2 = h * W_loca[2 * HID + t];
    p0 = warp_sum(p0); p1 = warp_sum(p1); p2 = warp_sum(p2);
    if (lane == 0) { sred[0][w] = p0; sred[1][w] = p1; sred[2][w] = p2; }

    __half* xh = d_xrh + (size_t)row * KREL;
    __half* xl = d_xrl + (size_t)row * KREL;
    wpair(xh, xl, XR_HL + t, h);
    if (t < 3)  wpair(xh, xl, XR_ZWL + t, zwhere_last[inrow * 3 + t]);
    if (t < 50) wpair(xh, xl, XR_ZWHATL + t, zwhat_last[inrow * 50 + t]);
    __syncthreads();
    if (t < 3) {
        float s = 0.0f;
#pragma unroll
        for (int q = 0; q < 8; q++) s += sred[t][q];
        s += b_loca[t];
        szw[t] = fmaxf(s, 0.0f) + zwhere_last[inrow * 3 + t];
    }
    __syncthreads();
    glimpse_pair(img + (size_t)n * IMG_HW, szw[0], szw[1], szw[2],
                 d_G1h + (size_t)row * KENC, d_G1l + (size_t)row * KENC, t);
}

// ---------------- HMMA fp16 2-term GEMM, fused epilogues ----------------
// CTA 64x128 (MxN), BK=32, 4-stage cp.async, 2 CTAs/SM.
// A split (hi,lo) fp16; B single fp16. 2 MMAs per k16 instead of 3.
// smem rows stride 80B (gcd(5,8)=1 -> ldmatrix conflict-free).
// Stage: Ah(64r) | Al(64r) | B(128r) = 256 rows * 80B = 20480B
// EPI 0: rel LSTM pointwise (write d_cr, d_hr)
// EPI 1: relu -> (hi,lo) fp16 out (enc)
// EPI 2: tem LSTM pointwise (read d_cr, write htemp_out)
#define ROW_B 80
#define OFF_AL (64 * ROW_B)          // 5120
#define OFF_B  (128 * ROW_B)         // 10240
#define STAGE_B (256 * ROW_B)        // 20480
#define SMEM_REQ (4 * STAGE_B)       // 81920

template <int EPI>
__global__ __launch_bounds__(256, 2) void hmma_gemm(
    const __half* __restrict__ Ah, const __half* __restrict__ Al, int lda,
    const __half* __restrict__ B, int ldb,
    const float* __restrict__ bias,
    float* __restrict__ cstate, float* __restrict__ hout,
    __half* __restrict__ Chi, __half* __restrict__ Clo,
    int ldc, int K, int nReal, int kk) {
    extern __shared__ char smem[];
    const uint32_t sb = smem_u32(smem);
    const int tid = threadIdx.x;
    const int lane = tid & 31, wid = tid >> 5;
    const int wm = wid >> 2, wn = wid & 3;      // 2 x 4 warp grid; warp tile 32x32
    const int bm = blockIdx.y * 64, bn = blockIdx.x * 128;
    const int nK = K / 32;

    float acc[2][4][4];
#pragma unroll
    for (int i = 0; i < 2; i++)
#pragma unroll
        for (int j = 0; j < 4; j++)
#pragma unroll
            for (int q = 0; q < 4; q++) acc[i][j][q] = 0.0f;

    auto load_stage = [&](int st, int kt) {
        int k0 = kt * 32;
        uint32_t base = sb + st * STAGE_B;
        // 256 rows * 4 chunks of 16B = 1024 cp.async ops; 256 threads -> 4 each
#pragma unroll
        for (int q = 0; q < 4; q++) {
            int idx = q * 256 + tid;          // 0..1023
            int row = idx >> 2;               // 0..255
            int ch = idx & 3;                 // 0..3
            const __half* gp;
            if (row < 64)       gp = Ah + (size_t)(bm + row) * lda + k0 + ch * 8;
            else if (row < 128) gp = Al + (size_t)(bm + row - 64) * lda + k0 + ch * 8;
            else                gp = B + (size_t)(bn + row - 128) * ldb + k0 + ch * 8;
            cp16(base + row * ROW_B + ch * 16, gp);
        }
        cp_commit();
    };

    load_stage(0, 0);
    if (nK > 1) load_stage(1, 1);
    if (nK > 2) load_stage(2, 2);
    int st = 0;
    for (int kt = 0; kt < nK; kt++) {
        if (kt + 3 < nK) { load_stage((kt + 3) & 3, kt + 3); cp_wait3(); }
        else if (kt + 2 < nK) cp_wait2();
        else if (kt + 1 < nK) cp_wait1();
        else cp_wait0();
        __syncthreads();
        uint32_t base = sb + st * STAGE_B;
        st = (st + 1) & 3;
#pragma unroll
        for (int ks = 0; ks < 2; ks++) {
            uint32_t ah[2][4], al[2][4], bh[4][2];
#pragma unroll
            for (int mf = 0; mf < 2; mf++) {
                int row = wm * 32 + mf * 16 + (lane & 15);
                int ch = ks * 2 + (lane >> 4);
                uint32_t a = base + row * ROW_B + ch * 16;
                ldm_x4(ah[mf], a);
                ldm_x4(al[mf], a + OFF_AL);
            }
#pragma unroll
            for (int nf = 0; nf < 4; nf++) {
                int row = wn * 32 + nf * 8 + (lane & 7);
                int ch = ks * 2 + ((lane >> 3) & 1);
                ldm_x2(bh[nf], base + OFF_B + row * ROW_B + ch * 16);
            }
#pragma unroll
            for (int mf = 0; mf < 2; mf++)
#pragma unroll
                for (int nf = 0; nf < 4; nf++) {
                    mma_f16(acc[mf][nf], ah[mf], bh[nf]);
                    mma_f16(acc[mf][nf], al[mf], bh[nf]);
                }
        }
        __syncthreads();
    }

    // epilogue
    int trow = lane >> 2, tcol2 = (lane & 3) * 2;
    bool evn = ((lane & 1) == 0);   // holds (i,f); odd holds (g,o)
#pragma unroll
    for (int mf = 0; mf < 2; mf++) {
        int r0 = bm + wm * 32 + mf * 16 + trow;
#pragma unroll
        for (int nf = 0; nf < 4; nf++) {
            int col = bn + wn * 32 + nf * 8 + tcol2;
            if (EPI == 1) {
#pragma unroll
                for (int e = 0; e < 4; e++) {
                    int cc = col + (e & 1);
                    int rr = r0 + (e >> 1) * 8;
                    if (cc < nReal) {
                        float v = fmaxf(acc[mf][nf][e] + bias[cc], 0.0f);
                        wpair(Chi + (size_t)rr * ldc, Clo + (size_t)rr * ldc, cc, v);
                    }
                }
            } else {
                int u = col >> 2;  // hidden unit
                float b0 = bias[col], b1 = bias[col + 1];
                float x0 = acc[mf][nf][0] + b0, x1 = acc[mf][nf][1] + b1;
                float x2 = acc[mf][nf][2] + b0, x3 = acc[mf][nf][3] + b1;
                float vA0, vB0, vA1, vB1;
                if (evn) { vA0 = sigm(x0); vB0 = sigm(x1); vA1 = sigm(x2); vB1 = sigm(x3); }
                else     { vA0 = tanhf(x0); vB0 = sigm(x1); vA1 = tanhf(x2); vB1 = sigm(x3); }
                // exchange: even receives tanh(g); odd receives sigm(i) (unused)
                float tA0 = __shfl_xor_sync(0xffffffffu, vA0, 1);
                float tA1 = __shfl_xor_sync(0xffffffffu, vA1, 1);
                float c20 = 0.0f, c21 = 0.0f;
                if (evn) {
                    float co0 = cstate[(size_t)r0 * HID + u];
                    float co1 = cstate[(size_t)(r0 + 8) * HID + u];
                    c20 = vB0 * co0 + vA0 * tA0;
                    c21 = vB1 * co1 + vA1 * tA1;
                    if (EPI == 0) {
                        cstate[(size_t)r0 * HID + u] = c20;
                        cstate[(size_t)(r0 + 8) * HID + u] = c21;
                    }
                }
                float cr0 = __shfl_xor_sync(0xffffffffu, c20, 1);
                float cr1 = __shfl_xor_sync(0xffffffffu, c21, 1);
                if (!evn) {
                    float h0 = vB0 * tanhf(cr0);
                    float h1 = vB1 * tanhf(cr1);
                    if (EPI == 0) {
                        hout[(size_t)r0 * HID + u] = h0;
                        hout[(size_t)(r0 + 8) * HID + u] = h1;
                    } else {   // EPI == 2: write h_t to output [n, k, HID]
                        hout[((size_t)r0 * KS + kk) * HID + u] = h0;
                        hout[((size_t)(r0 + 8) * KS + kk) * HID + u] = h1;
                    }
                }
            }
        }
    }
}

// ---------------- rel stage 2: zw linear + glimpse2 + xtem pack ----------------
__global__ __launch_bounds__(256) void relglimpse2_kernel(
    const float* __restrict__ img, const float* __restrict__ hidden_last,
    const float* __restrict__ zwhere_last, const float* __restrict__ zwhat_last,
    const float* __restrict__ Wm_wh, const float* __restrict__ bm_wh,
    const float* __restrict__ zwhat_out, float* __restrict__ zwhere_out, int k) {
    int n = blockIdx.x, t = threadIdx.x;
    __shared__ float hs[HID];
    __shared__ float sred[3][8];
    __shared__ float szw[3];
    int w = t >> 5, lane = t & 31;

    float h = d_hr[n * HID + t];    // h_r2 from rel GEMM epilogue
    hs[t] = h;

    __half* xh = d_xth + (size_t)n * KTEM;
    __half* xl = d_xtl + (size_t)n * KTEM;
    wpair(xh, xl, XT_HR + t, h);
    wpair(xh, xl, XT_HL + t, hidden_last[((size_t)n * KS + k) * HID + t]);
    if (t < 3) wpair(xh, xl, XT_PZW + t, k ? zwhere_out[((size_t)n * KS + k - 1) * 3 + t] : 0.0f);
    if (t < 50) {
        wpair(xh, xl, XT_ZWHATL + t, zwhat_last[((size_t)n * KS + k) * 50 + t]);
        wpair(xh, xl, XT_PZWHAT + t, k ? zwhat_out[((size_t)n * KS + k - 1) * 50 + t] : 0.0f);
    }
    __syncthreads();

    // zw = [zwl(3), h_r2(256)] @ Wm_wh^T + bm_wh (K=259)
    float c0 = (t < 3) ? zwhere_last[((size_t)n * KS + k) * 3 + t] : hs[t - 3];
    float q0 = c0 * Wm_wh[t];
    float q1 = c0 * Wm_wh[259 + t];
    float q2 = c0 * Wm_wh[518 + t];
    if (t < 3) {
        float c1 = hs[253 + t];
        q0 += c1 * Wm_wh[256 + t];
        q1 += c1 * Wm_wh[259 + 256 + t];
        q2 += c1 * Wm_wh[518 + 256 + t];
    }
    q0 = warp_sum(q0); q1 = warp_sum(q1); q2 = warp_sum(q2);
    if (lane == 0) { sred[0][w] = q0; sred[1][w] = q1; sred[2][w] = q2; }
    __syncthreads();
    if (t < 3) {
        float s = 0.0f;
#pragma unroll
        for (int q = 0; q < 8; q++) s += sred[t][q];
        s += bm_wh[t];
        szw[t] = s;
        zwhere_out[((size_t)n * KS + k) * 3 + t] = s;
        wpair(xh, xl, XT_ZW + t, s);
    }
    __syncthreads();
    glimpse_pair(img + (size_t)n * IMG_HW, szw[0], szw[1], szw[2], xh, xl, t);
}

// ---------------- head: zwhat GEMV + presence + fused recpack for step k+1 ----------------
__global__ __launch_bounds__(256) void head_kernel(
    const float* __restrict__ zwhat_last, const float* __restrict__ zpres_last,
    const float* __restrict__ Wm_wt, const float* __restrict__ bm_wt,
    const float* __restrict__ Wm_pr, const float* __restrict__ bm_pr,
    const float* __restrict__ Ws_pr, const float* __restrict__ bs_pr,
    const float* __restrict__ zwhere_out, float* __restrict__ zwhat_out,
    float* __restrict__ zpres_out, const float* __restrict__ htemp_out, int k) {
    int n = blockIdx.x, t = threadIdx.x;
    __shared__ float xs[562];
    __shared__ float ys[565];
    __shared__ float red[16];
    int w = t >> 5, lane = t & 31;

    float ht = htemp_out[((size_t)n * KS + k) * HID + t];  // from tem GEMM epilogue
    float hr = d_hr[n * HID + t];
    xs[50 + t] = hr; xs[306 + t] = ht;
    ys[53 + t] = hr; ys[309 + t] = ht;
    if (t < 50) xs[t] = zwhat_last[((size_t)n * KS + k) * 50 + t];
    if (t < 3) ys[50 + t] = zwhere_out[((size_t)n * KS + k) * 3 + t];
    __syncthreads();

    for (int j = w; j < 50; j += 8) {
        const float* wr = Wm_wt + (size_t)j * 562;
        float acc = 0.0f;
        for (int i = lane; i < 562; i += 32) acc += xs[i] * wr[i];
        acc = warp_sum(acc);
        if (lane == 0) {
            float z = acc + bm_wt[j];
            ys[j] = z;
            zwhat_out[((size_t)n * KS + k) * 50 + j] = z;
        }
    }
    __syncthreads();

    // fused recpack for step k+1 (k-major xrel rows (k+1)*NB + n)
    if (k < KS - 1) {
        size_t row = (size_t)(k + 1) * NB + n;
        __half* xh = d_xrh + row * KREL;
        __half* xl = d_xrl + row * KREL;
        wpair(xh, xl, XR_HR + t, hr);
        if (t < 3)  wpair(xh, xl, XR_PZW + t, ys[50 + t]);
        if (t < 50) wpair(xh, xl, XR_PZWHAT + t, ys[t]);
    }

    // presence: two 565-dots across the block
    float am = 0.0f, as = 0.0f;
    for (int i = t; i < 565; i += 256) {
        float x = ys[i];
        am += x * Wm_pr[i];
        as += x * Ws_pr[i];
    }
    am = warp_sum(am); as = warp_sum(as);
    if (lane == 0) { red[w] = am; red[8 + w] = as; }
    __syncthreads();
    if (t == 0) {
        float m = 0.0f, s = 0.0f;
#pragma unroll
        for (int q = 0; q < 8; q++) { m += red[q]; s += red[8 + q]; }
        float p = sigm(m + bm_pr[0]) * sigm(s + bs_pr[0]);
        zpres_out[(size_t)n * KS + k] = p * zpres_last[(size_t)n * KS + k];
    }
}

// ---------------- host ----------------
extern "C" void kernel_launch(void* const* d_in, const int* in_sizes, int n_in,
                              void* d_out, int out_size) {
    const float* img         = (const float*)d_in[0];
    const float* zwhat_last  = (const float*)d_in[1];
    const float* zwhere_last = (const float*)d_in[2];
    const float* zpres_last  = (const float*)d_in[3];
    const float* hidden_last = (const float*)d_in[4];
    const float* W_loca = (const float*)d_in[5];
    const float* b_loca = (const float*)d_in[6];
    const float* Wg     = (const float*)d_in[7];
    const float* bg     = (const float*)d_in[8];
    const float* Wih_rel = (const float*)d_in[9];
    const float* Whh_rel = (const float*)d_in[10];
    const float* bih_rel = (const float*)d_in[11];
    const float* bhh_rel = (const float*)d_in[12];
    const float* Wih_tem = (const float*)d_in[13];
    const float* Whh_tem = (const float*)d_in[14];
    const float* bih_tem = (const float*)d_in[15];
    const float* bhh_tem = (const float*)d_in[16];
    const float* Wm_wh = (const float*)d_in[17];
    const float* bm_wh = (const float*)d_in[18];
    const float* Wm_wt = (const float*)d_in[21];
    const float* bm_wt = (const float*)d_in[22];
    const float* Wm_pr = (const float*)d_in[25];
    const float* bm_pr = (const float*)d_in[26];
    const float* Ws_pr = (const float*)d_in[27];
    const float* bs_pr = (const float*)d_in[28];

    float* out = (float*)d_out;
    float* zwhat_out  = out;
    float* zwhere_out = out + (size_t)NB * KS * 50;
    float* zpres_out  = zwhere_out + (size_t)NB * KS * 3;
    float* htemp_out  = zpres_out + (size_t)NB * KS * 1;

    void *pG1h, *pG1l, *pXrh, *pXrl, *pXth, *pXtl;
    void *pWr, *pWt, *pWg, *pBrel, *pBtem, *pHr, *pCr;
    cudaGetSymbolAddress(&pG1h, d_G1h); cudaGetSymbolAddress(&pG1l, d_G1l);
    cudaGetSymbolAddress(&pXrh, d_xrh); cudaGetSymbolAddress(&pXrl, d_xrl);
    cudaGetSymbolAddress(&pXth, d_xth); cudaGetSymbolAddress(&pXtl, d_xtl);
    cudaGetSymbolAddress(&pWr, d_Wr); cudaGetSymbolAddress(&pWt, d_Wt);
    cudaGetSymbolAddress(&pWg, d_Wg);
    cudaGetSymbolAddress(&pBrel, d_brel); cudaGetSymbolAddress(&pBtem, d_btem);
    cudaGetSymbolAddress(&pHr, d_hr); cudaGetSymbolAddress(&pCr, d_cr);

    cudaFuncSetAttribute(hmma_gemm<0>, cudaFuncAttributeMaxDynamicSharedMemorySize, SMEM_REQ);
    cudaFuncSetAttribute(hmma_gemm<1>, cudaFuncAttributeMaxDynamicSharedMemorySize, SMEM_REQ);
    cudaFuncSetAttribute(hmma_gemm<2>, cudaFuncAttributeMaxDynamicSharedMemorySize, SMEM_REQ);

    prep_kernel<<<2048, 256>>>(Wih_rel, Whh_rel, bih_rel, bhh_rel,
                               Wih_tem, Whh_tem, bih_tem, bhh_tem, Wg);
    staticpack_kernel<<<NB * KS, 256>>>(img, hidden_last, zwhere_last, zwhat_last,
                                        W_loca, b_loca);
    // enc GEMM: M=16384, N=128(100 real), K=2560 -> xrel[:,0:100] hi/lo
    {
        dim3 grid(1, NB * KS / 64);
        hmma_gemm<1><<<grid, 256, SMEM_REQ>>>(
            (const __half*)pG1h, (const __half*)pG1l, KENC,
            (const __half*)pWg, KENC,
            bg, nullptr, nullptr,
            (__half*)pXrh, (__half*)pXrl, KREL,
            KENC, 100, 0);
    }
    for (int k = 0; k < KS; k++) {
        // rel gates GEMM + LSTM epilogue: M=2048 (k-major rows), N=1024, K=768
        {
            dim3 grid(NGATE / 128, NB / 64);
            hmma_gemm<0><<<grid, 256, SMEM_REQ>>>(
                (const __half*)pXrh + (size_t)k * NB * KREL,
                (const __half*)pXrl + (size_t)k * NB * KREL, KREL,
                (const __half*)pWr, KREL,
                (const float*)pBrel, (float*)pCr, (float*)pHr,
                nullptr, nullptr, 0, KREL, NGATE, k);
        }
        relglimpse2_kernel<<<NB, 256>>>(img, hidden_last, zwhere_last, zwhat_last,
                                        Wm_wh, bm_wh, zwhat_out, zwhere_out, k);
        // tem gates GEMM + LSTM epilogue (writes htemp_out): M=2048, N=1024, K=3136
        {
            dim3 grid(NGATE / 128, NB / 64);
            hmma_gemm<2><<<grid, 256, SMEM_REQ>>>(
                (const __half*)pXth, (const __half*)pXtl, KTEM,
                (const __half*)pWt, KTEM,
                (const float*)pBtem, (float*)pCr, htemp_out,
                nullptr, nullptr, 0, KTEM, NGATE, k);
        }
        head_kernel<<<NB, 256>>>(zwhat_last, zpres_last, Wm_wt, bm_wt,
                                 Wm_pr, bm_pr, Ws_pr, bs_pr,
                                 zwhere_out, zwhat_out, zpres_out, htemp_out, k);
    }
}

// round 11
// speedup vs baseline: 1.4526x; 1.0931x over previous
#include <cuda_runtime.h>
#include <cuda_fp16.h>
#include <cstdint>
#include <math.h>

#define NB   2048
#define KS   8
#define HID  256
#define IMG_HW 16384

#define KENC 2560   // glimpse K padded (2500 real)
#define KREL 768    // rel K padded (718 real)
#define KTEM 3136   // tem K padded (3118 real)
#define NGATE 1024

// xrel col offsets: [enc100|zwl3|pzw3|zwhatl50|pzwhat50|hl256|h_r256]
#define XR_ZWL 100
#define XR_PZW 103
#define XR_ZWHATL 106
#define XR_PZWHAT 156
#define XR_HL  206
#define XR_HR  462
// xtem col offsets: [g2 2500|zw3|pzw3|zwhatl50|pzwhat50|hl256|h_r2 256]
#define XT_ZW 2500
#define XT_PZW 2503
#define XT_ZWHATL 2506
#define XT_PZWHAT 2556
#define XT_HL 2606
#define XT_HR 2862

// ---------------- scratch ----------------
// activations as fp16 (hi, lo) pairs; k-major layout: row = k*NB + n
__device__ __half d_G1h[(size_t)NB * KS * KENC];
__device__ __half d_G1l[(size_t)NB * KS * KENC];
__device__ __half d_xrh[(size_t)NB * KS * KREL];
__device__ __half d_xrl[(size_t)NB * KS * KREL];
__device__ __half d_xth[(size_t)NB * KTEM];
__device__ __half d_xtl[(size_t)NB * KTEM];
__device__ float d_hr[(size_t)NB * HID];
__device__ float d_cr[(size_t)NB * HID];
// weights: single fp16, gate-interleaved rows (row' = unit*4 + gate)
__device__ __half d_Wr[(size_t)NGATE * KREL];
__device__ __half d_Wt[(size_t)NGATE * KTEM];
__device__ __half d_Wg[(size_t)128 * KENC];
__device__ float d_brel[NGATE];
__device__ float d_btem[NGATE];

// ---------------- ptx helpers (sm_80-era, safe for compute_103 PTX) ----------------
__device__ __forceinline__ uint32_t smem_u32(const void* p) {
    uint32_t a;
    asm("{ .reg .u64 t; cvta.to.shared.u64 t, %1; cvt.u32.u64 %0, t; }" : "=r"(a) : "l"(p));
    return a;
}
__device__ __forceinline__ void cp16(uint32_t dst, const void* src) {
    asm volatile("cp.async.ca.shared.global [%0], [%1], 16;" :: "r"(dst), "l"(src));
}
__device__ __forceinline__ void cp_commit() { asm volatile("cp.async.commit_group;"); }
__device__ __forceinline__ void cp_wait3() { asm volatile("cp.async.wait_group 3;"); }
__device__ __forceinline__ void cp_wait2() { asm volatile("cp.async.wait_group 2;"); }
__device__ __forceinline__ void cp_wait1() { asm volatile("cp.async.wait_group 1;"); }
__device__ __forceinline__ void cp_wait0() { asm volatile("cp.async.wait_group 0;"); }
__device__ __forceinline__ void ldm_x4(uint32_t* r, uint32_t a) {
    asm volatile("ldmatrix.sync.aligned.m8n8.x4.shared.b16 {%0,%1,%2,%3}, [%4];"
                 : "=r"(r[0]), "=r"(r[1]), "=r"(r[2]), "=r"(r[3]) : "r"(a));
}
__device__ __forceinline__ void ldm_x2(uint32_t* r, uint32_t a) {
    asm volatile("ldmatrix.sync.aligned.m8n8.x2.shared.b16 {%0,%1}, [%2];"
                 : "=r"(r[0]), "=r"(r[1]) : "r"(a));
}
__device__ __forceinline__ void mma_f16(float* c, const uint32_t* a, const uint32_t* b) {
    asm volatile("mma.sync.aligned.m16n8k16.row.col.f32.f16.f16.f32 "
                 "{%0,%1,%2,%3}, {%4,%5,%6,%7}, {%8,%9}, {%0,%1,%2,%3};"
                 : "+f"(c[0]), "+f"(c[1]), "+f"(c[2]), "+f"(c[3])
                 : "r"(a[0]), "r"(a[1]), "r"(a[2]), "r"(a[3]), "r"(b[0]), "r"(b[1]));
}

// ---------------- math helpers ----------------
__device__ __forceinline__ float sigm(float x) { return 1.0f / (1.0f + expf(-x)); }
__device__ __forceinline__ float warp_sum(float v) {
#pragma unroll
    for (int o = 16; o; o >>= 1) v += __shfl_xor_sync(0xffffffffu, v, o);
    return v;
}
// split fp32 -> fp16 hi + fp16 lo
__device__ __forceinline__ void wpair(__half* ph, __half* pl, int i, float x) {
    __half h = __float2half(x);
    ph[i] = h;
    pl[i] = __float2half(x - __half2float(h));
}
__device__ __forceinline__ float samp(const float* __restrict__ im, int y, int x) {
    if ((unsigned)y < 128u && (unsigned)x < 128u) return im[(y << 7) + x];
    return 0.0f;
}
__device__ __forceinline__ float bilin(const float* __restrict__ imgN,
                                       float s, float tx, float ty, int g) {
    int iy = g / 50, ix = g - iy * 50;
    float gx = -1.0f + (float)ix * (2.0f / 49.0f);
    float gy = -1.0f + (float)iy * (2.0f / 49.0f);
    float px = (s * gx + tx + 1.0f) * 0.5f * 127.0f;
    float py = (s * gy + ty + 1.0f) * 0.5f * 127.0f;
    float x0f = floorf(px), y0f = floorf(py);
    float wx1 = px - x0f, wy1 = py - y0f;
    int x0 = (int)x0f, y0 = (int)y0f;
    float v00 = samp(imgN, y0, x0),     v01 = samp(imgN, y0, x0 + 1);
    float v10 = samp(imgN, y0 + 1, x0), v11 = samp(imgN, y0 + 1, x0 + 1);
    return (1.0f - wy1) * (1.0f - wx1) * v00 + (1.0f - wy1) * wx1 * v01
         + wy1 * (1.0f - wx1) * v10 + wy1 * wx1 * v11;
}
__device__ __forceinline__ void glimpse_pair(const float* __restrict__ imgN,
                                             float s, float tx, float ty,
                                             __half* __restrict__ dh,
                                             __half* __restrict__ dl, int t) {
    for (int g = t; g < 2500; g += 256) {
        float r = bilin(imgN, s, tx, ty, g);
        wpair(dh, dl, g, r);
    }
}
// hi-only glimpse (tem GEMM uses single-term fp16 for the g2 block)
__device__ __forceinline__ void glimpse_hi(const float* __restrict__ imgN,
                                           float s, float tx, float ty,
                                           __half* __restrict__ dh, int t) {
    for (int g = t; g < 2500; g += 256) {
        dh[g] = __float2half(bilin(imgN, s, tx, ty, g));
    }
}

// ---------------- prep ----------------
__global__ void prep_kernel(const float* __restrict__ Wih_rel, const float* __restrict__ Whh_rel,
                            const float* __restrict__ bih_rel, const float* __restrict__ bhh_rel,
                            const float* __restrict__ Wih_tem, const float* __restrict__ Whh_tem,
                            const float* __restrict__ bih_tem, const float* __restrict__ bhh_tem,
                            const float* __restrict__ Wg) {
    int tid = blockIdx.x * blockDim.x + threadIdx.x;
    int nt = gridDim.x * blockDim.x;
    // gate-interleaved: out row r' -> unit u=r'>>2, gate g=r'&3, orig row = g*256+u
    for (int i = tid; i < NGATE * KREL; i += nt) {
        int rp = i / KREL, c = i - rp * KREL;
        int orig = (rp & 3) * 256 + (rp >> 2);
        float v = 0.0f;
        if (c < 462) v = Wih_rel[orig * 462 + c];
        else if (c < 718) v = Whh_rel[orig * 256 + (c - 462)];
        d_Wr[i] = __float2half(v);
    }
    for (int i = tid; i < NGATE * KTEM; i += nt) {
        int rp = i / KTEM, c = i - rp * KTEM;
        int orig = (rp & 3) * 256 + (rp >> 2);
        float v = 0.0f;
        if (c < 2862) v = Wih_tem[orig * 2862 + c];
        else if (c < 3118) v = Whh_tem[orig * 256 + (c - 2862)];
        d_Wt[i] = __float2half(v);
    }
    for (int i = tid; i < 128 * KENC; i += nt) {
        int r = i / KENC, c = i - r * KENC;
        float v = (r < 100 && c < 2500) ? Wg[r * 2500 + c] : 0.0f;
        d_Wg[i] = __float2half(v);
    }
    for (int i = tid; i < NGATE; i += nt) {
        int orig = (i & 3) * 256 + (i >> 2);
        d_brel[i] = bih_rel[orig] + bhh_rel[orig];
        d_btem[i] = bih_tem[orig] + bhh_tem[orig];
    }
    for (int i = tid; i < NB * HID; i += nt) { d_hr[i] = 0.0f; d_cr[i] = 0.0f; }
    // zero recurrent xrel cols for k=0 rows (rows 0..NB-1)
    __half z = __float2half(0.0f);
    for (int i = tid; i < NB * 3; i += nt) {
        int r = i / 3, c = XR_PZW + i % 3;
        d_xrh[(size_t)r * KREL + c] = z; d_xrl[(size_t)r * KREL + c] = z;
    }
    for (int i = tid; i < NB * 50; i += nt) {
        int r = i / 50, c = XR_PZWHAT + i % 50;
        d_xrh[(size_t)r * KREL + c] = z; d_xrl[(size_t)r * KREL + c] = z;
    }
    for (int i = tid; i < NB * HID; i += nt) {
        int r = i / HID, c = XR_HR + i % HID;
        d_xrh[(size_t)r * KREL + c] = z; d_xrl[(size_t)r * KREL + c] = z;
    }
    // pads
    for (int i = tid; i < NB * KS * 60; i += nt) {
        int r = i / 60, c = 2500 + i % 60;
        d_G1h[(size_t)r * KENC + c] = z; d_G1l[(size_t)r * KENC + c] = z;
    }
    for (int i = tid; i < NB * KS * 50; i += nt) {
        int r = i / 50, c = 718 + i % 50;
        d_xrh[(size_t)r * KREL + c] = z; d_xrl[(size_t)r * KREL + c] = z;
    }
    for (int i = tid; i < NB * 18; i += nt) {
        int r = i / 18, c = 3118 + i % 18;
        d_xth[(size_t)r * KTEM + c] = z; d_xtl[(size_t)r * KTEM + c] = z;
    }
    // zero xtl in the single-term g2 region never written again (cols < XT_ZW),
    // so stale garbage can never leak if split boundary changes
    for (size_t i = tid; i < (size_t)NB * XT_ZW; i += nt) {
        size_t r = i / XT_ZW, c = i % XT_ZW;
        d_xtl[r * KTEM + c] = z;
    }
}

// ---------------- static pack: zwb + glimpse1 + static xrel cols, all (n,k) ----------------
__global__ __launch_bounds__(256) void staticpack_kernel(
    const float* __restrict__ img, const float* __restrict__ hidden_last,
    const float* __restrict__ zwhere_last, const float* __restrict__ zwhat_last,
    const float* __restrict__ W_loca, const float* __restrict__ b_loca) {
    int row = blockIdx.x, t = threadIdx.x;   // row = k*NB + n
    int k = row / NB, n = row - k * NB;
    size_t inrow = (size_t)n * KS + k;
    __shared__ float sred[3][8];
    __shared__ float szw[3];
    int w = t >> 5, lane = t & 31;

    float h = hidden_last[inrow * HID + t];
    float p0 = h * W_loca[t];
    float p1 = h * W_loca[HID + t];
    float p2 = h * W_loca[2 * HID + t];
    p0 = warp_sum(p0); p1 = warp_sum(p1); p2 = warp_sum(p2);
    if (lane == 0) { sred[0][w] = p0; sred[1][w] = p1; sred[2][w] = p2; }

    __half* xh = d_xrh + (size_t)row * KREL;
    __half* xl = d_xrl + (size_t)row * KREL;
    wpair(xh, xl, XR_HL + t, h);
    if (t < 3)  wpair(xh, xl, XR_ZWL + t, zwhere_last[inrow * 3 + t]);
    if (t < 50) wpair(xh, xl, XR_ZWHATL + t, zwhat_last[inrow * 50 + t]);
    __syncthreads();
    if (t < 3) {
        float s = 0.0f;
#pragma unroll
        for (int q = 0; q < 8; q++) s += sred[t][q];
        s += b_loca[t];
        szw[t] = fmaxf(s, 0.0f) + zwhere_last[inrow * 3 + t];
    }
    __syncthreads();
    glimpse_pair(img + (size_t)n * IMG_HW, szw[0], szw[1], szw[2],
                 d_G1h + (size_t)row * KENC, d_G1l + (size_t)row * KENC, t);
}

// ---------------- HMMA fp16 GEMM with asymmetric 2-term split ----------------
// CTA 64x128 (MxN), BK=32, 4-stage cp.async, 2 CTAs/SM.
// A split (hi,lo) fp16; B single fp16. Chunks with k0 < splitK use ONLY the hi
// term (1 MMA per k16); chunks with k0 >= splitK use hi+lo (2 MMAs).
// smem rows stride 80B (gcd(5,8)=1 -> ldmatrix conflict-free).
// Stage: Ah(64r) | Al(64r) | B(128r) = 256 rows * 80B = 20480B
// EPI 0: rel LSTM pointwise (write d_cr, d_hr)
// EPI 1: relu -> (hi,lo) fp16 out (enc)
// EPI 2: tem LSTM pointwise (read d_cr, write htemp_out)
#define ROW_B 80
#define OFF_AL (64 * ROW_B)          // 5120
#define OFF_B  (128 * ROW_B)         // 10240
#define STAGE_B (256 * ROW_B)        // 20480
#define SMEM_REQ (4 * STAGE_B)       // 81920

template <int EPI>
__global__ __launch_bounds__(256, 2) void hmma_gemm(
    const __half* __restrict__ Ah, const __half* __restrict__ Al, int lda,
    const __half* __restrict__ B, int ldb,
    const float* __restrict__ bias,
    float* __restrict__ cstate, float* __restrict__ hout,
    __half* __restrict__ Chi, __half* __restrict__ Clo,
    int ldc, int K, int splitK, int nReal, int kk) {
    extern __shared__ char smem[];
    const uint32_t sb = smem_u32(smem);
    const int tid = threadIdx.x;
    const int lane = tid & 31, wid = tid >> 5;
    const int wm = wid >> 2, wn = wid & 3;      // 2 x 4 warp grid; warp tile 32x32
    const int bm = blockIdx.y * 64, bn = blockIdx.x * 128;
    const int nK = K / 32;

    float acc[2][4][4];
#pragma unroll
    for (int i = 0; i < 2; i++)
#pragma unroll
        for (int j = 0; j < 4; j++)
#pragma unroll
            for (int q = 0; q < 4; q++) acc[i][j][q] = 0.0f;

    auto load_stage = [&](int st, int kt) {
        int k0 = kt * 32;
        bool dual = (k0 >= splitK);
        uint32_t base = sb + st * STAGE_B;
        // 256 rows * 4 chunks of 16B; skip Al rows (64..127) for single-term chunks
#pragma unroll
        for (int q = 0; q < 4; q++) {
            int idx = q * 256 + tid;          // 0..1023
            int row = idx >> 2;               // 0..255
            int ch = idx & 3;                 // 0..3
            const __half* gp;
            if (row < 64)       gp = Ah + (size_t)(bm + row) * lda + k0 + ch * 8;
            else if (row < 128) {
                if (!dual) continue;
                gp = Al + (size_t)(bm + row - 64) * lda + k0 + ch * 8;
            }
            else                gp = B + (size_t)(bn + row - 128) * ldb + k0 + ch * 8;
            cp16(base + row * ROW_B + ch * 16, gp);
        }
        cp_commit();
    };

    load_stage(0, 0);
    if (nK > 1) load_stage(1, 1);
    if (nK > 2) load_stage(2, 2);
    int st = 0;
    for (int kt = 0; kt < nK; kt++) {
        if (kt + 3 < nK) { load_stage((kt + 3) & 3, kt + 3); cp_wait3(); }
        else if (kt + 2 < nK) cp_wait2();
        else if (kt + 1 < nK) cp_wait1();
        else cp_wait0();
        __syncthreads();
        uint32_t base = sb + st * STAGE_B;
        st = (st + 1) & 3;
        bool dual = (kt * 32 >= splitK);
#pragma unroll
        for (int ks = 0; ks < 2; ks++) {
            uint32_t ah[2][4], al[2][4], bh[4][2];
#pragma unroll
            for (int mf = 0; mf < 2; mf++) {
                int row = wm * 32 + mf * 16 + (lane & 15);
                int ch = ks * 2 + (lane >> 4);
                uint32_t a = base + row * ROW_B + ch * 16;
                ldm_x4(ah[mf], a);
                if (dual) ldm_x4(al[mf], a + OFF_AL);
            }
#pragma unroll
            for (int nf = 0; nf < 4; nf++) {
                int row = wn * 32 + nf * 8 + (lane & 7);
                int ch = ks * 2 + ((lane >> 3) & 1);
                ldm_x2(bh[nf], base + OFF_B + row * ROW_B + ch * 16);
            }
#pragma unroll
            for (int mf = 0; mf < 2; mf++)
#pragma unroll
                for (int nf = 0; nf < 4; nf++) {
                    mma_f16(acc[mf][nf], ah[mf], bh[nf]);
                    if (dual) mma_f16(acc[mf][nf], al[mf], bh[nf]);
                }
        }
        __syncthreads();
    }

    // epilogue
    int trow = lane >> 2, tcol2 = (lane & 3) * 2;
    bool evn = ((lane & 1) == 0);   // holds (i,f); odd holds (g,o)
#pragma unroll
    for (int mf = 0; mf < 2; mf++) {
        int r0 = bm + wm * 32 + mf * 16 + trow;
#pragma unroll
        for (int nf = 0; nf < 4; nf++) {
            int col = bn + wn * 32 + nf * 8 + tcol2;
            if (EPI == 1) {
#pragma unroll
                for (int e = 0; e < 4; e++) {
                    int cc = col + (e & 1);
                    int rr = r0 + (e >> 1) * 8;
                    if (cc < nReal) {
                        float v = fmaxf(acc[mf][nf][e] + bias[cc], 0.0f);
                        wpair(Chi + (size_t)rr * ldc, Clo + (size_t)rr * ldc, cc, v);
                    }
                }
            } else {
                int u = col >> 2;  // hidden unit
                float b0 = bias[col], b1 = bias[col + 1];
                float x0 = acc[mf][nf][0] + b0, x1 = acc[mf][nf][1] + b1;
                float x2 = acc[mf][nf][2] + b0, x3 = acc[mf][nf][3] + b1;
                float vA0, vB0, vA1, vB1;
                if (evn) { vA0 = sigm(x0); vB0 = sigm(x1); vA1 = sigm(x2); vB1 = sigm(x3); }
                else     { vA0 = tanhf(x0); vB0 = sigm(x1); vA1 = tanhf(x2); vB1 = sigm(x3); }
                // exchange: even receives tanh(g); odd receives sigm(i) (unused)
                float tA0 = __shfl_xor_sync(0xffffffffu, vA0, 1);
                float tA1 = __shfl_xor_sync(0xffffffffu, vA1, 1);
                float c20 = 0.0f, c21 = 0.0f;
                if (evn) {
                    float co0 = cstate[(size_t)r0 * HID + u];
                    float co1 = cstate[(size_t)(r0 + 8) * HID + u];
                    c20 = vB0 * co0 + vA0 * tA0;
                    c21 = vB1 * co1 + vA1 * tA1;
                    if (EPI == 0) {
                        cstate[(size_t)r0 * HID + u] = c20;
                        cstate[(size_t)(r0 + 8) * HID + u] = c21;
                    }
                }
                float cr0 = __shfl_xor_sync(0xffffffffu, c20, 1);
                float cr1 = __shfl_xor_sync(0xffffffffu, c21, 1);
                if (!evn) {
                    float h0 = vB0 * tanhf(cr0);
                    float h1 = vB1 * tanhf(cr1);
                    if (EPI == 0) {
                        hout[(size_t)r0 * HID + u] = h0;
                        hout[(size_t)(r0 + 8) * HID + u] = h1;
                    } else {   // EPI == 2: write h_t to output [n, k, HID]
                        hout[((size_t)r0 * KS + kk) * HID + u] = h0;
                        hout[((size_t)(r0 + 8) * KS + kk) * HID + u] = h1;
                    }
                }
            }
        }
    }
}

// ---------------- rel stage 2: zw linear + glimpse2 + xtem pack ----------------
__global__ __launch_bounds__(256) void relglimpse2_kernel(
    const float* __restrict__ img, const float* __restrict__ hidden_last,
    const float* __restrict__ zwhere_last, const float* __restrict__ zwhat_last,
    const float* __restrict__ Wm_wh, const float* __restrict__ bm_wh,
    const float* __restrict__ zwhat_out, float* __restrict__ zwhere_out, int k) {
    int n = blockIdx.x, t = threadIdx.x;
    __shared__ float hs[HID];
    __shared__ float sred[3][8];
    __shared__ float szw[3];
    int w = t >> 5, lane = t & 31;

    float h = d_hr[n * HID + t];    // h_r2 from rel GEMM epilogue
    hs[t] = h;

    __half* xh = d_xth + (size_t)n * KTEM;
    __half* xl = d_xtl + (size_t)n * KTEM;
    wpair(xh, xl, XT_HR + t, h);
    wpair(xh, xl, XT_HL + t, hidden_last[((size_t)n * KS + k) * HID + t]);
    if (t < 3) wpair(xh, xl, XT_PZW + t, k ? zwhere_out[((size_t)n * KS + k - 1) * 3 + t] : 0.0f);
    if (t < 50) {
        wpair(xh, xl, XT_ZWHATL + t, zwhat_last[((size_t)n * KS + k) * 50 + t]);
        wpair(xh, xl, XT_PZWHAT + t, k ? zwhat_out[((size_t)n * KS + k - 1) * 50 + t] : 0.0f);
    }
    __syncthreads();

    // zw = [zwl(3), h_r2(256)] @ Wm_wh^T + bm_wh (K=259)
    float c0 = (t < 3) ? zwhere_last[((size_t)n * KS + k) * 3 + t] : hs[t - 3];
    float q0 = c0 * Wm_wh[t];
    float q1 = c0 * Wm_wh[259 + t];
    float q2 = c0 * Wm_wh[518 + t];
    if (t < 3) {
        float c1 = hs[253 + t];
        q0 += c1 * Wm_wh[256 + t];
        q1 += c1 * Wm_wh[259 + 256 + t];
        q2 += c1 * Wm_wh[518 + 256 + t];
    }
    q0 = warp_sum(q0); q1 = warp_sum(q1); q2 = warp_sum(q2);
    if (lane == 0) { sred[0][w] = q0; sred[1][w] = q1; sred[2][w] = q2; }
    __syncthreads();
    if (t < 3) {
        float s = 0.0f;
#pragma unroll
        for (int q = 0; q < 8; q++) s += sred[t][q];
        s += bm_wh[t];
        szw[t] = s;
        zwhere_out[((size_t)n * KS + k) * 3 + t] = s;
        wpair(xh, xl, XT_ZW + t, s);
    }
    __syncthreads();
    // g2 block is consumed single-term by the tem GEMM -> write hi only
    glimpse_hi(img + (size_t)n * IMG_HW, szw[0], szw[1], szw[2], xh, t);
}

// ---------------- head: zwhat GEMV + presence + fused recpack for step k+1 ----------------
__global__ __launch_bounds__(256) void head_kernel(
    const float* __restrict__ zwhat_last, const float* __restrict__ zpres_last,
    const float* __restrict__ Wm_wt, const float* __restrict__ bm_wt,
    const float* __restrict__ Wm_pr, const float* __restrict__ bm_pr,
    const float* __restrict__ Ws_pr, const float* __restrict__ bs_pr,
    const float* __restrict__ zwhere_out, float* __restrict__ zwhat_out,
    float* __restrict__ zpres_out, const float* __restrict__ htemp_out, int k) {
    int n = blockIdx.x, t = threadIdx.x;
    __shared__ float xs[562];
    __shared__ float ys[565];
    __shared__ float red[16];
    int w = t >> 5, lane = t & 31;

    float ht = htemp_out[((size_t)n * KS + k) * HID + t];  // from tem GEMM epilogue
    float hr = d_hr[n * HID + t];
    xs[50 + t] = hr; xs[306 + t] = ht;
    ys[53 + t] = hr; ys[309 + t] = ht;
    if (t < 50) xs[t] = zwhat_last[((size_t)n * KS + k) * 50 + t];
    if (t < 3) ys[50 + t] = zwhere_out[((size_t)n * KS + k) * 3 + t];
    __syncthreads();

    for (int j = w; j < 50; j += 8) {
        const float* wr = Wm_wt + (size_t)j * 562;
        float acc = 0.0f;
        for (int i = lane; i < 562; i += 32) acc += xs[i] * wr[i];
        acc = warp_sum(acc);
        if (lane == 0) {
            float z = acc + bm_wt[j];
            ys[j] = z;
            zwhat_out[((size_t)n * KS + k) * 50 + j] = z;
        }
    }
    __syncthreads();

    // fused recpack for step k+1 (k-major xrel rows (k+1)*NB + n)
    if (k < KS - 1) {
        size_t row = (size_t)(k + 1) * NB + n;
        __half* xh = d_xrh + row * KREL;
        __half* xl = d_xrl + row * KREL;
        wpair(xh, xl, XR_HR + t, hr);
        if (t < 3)  wpair(xh, xl, XR_PZW + t, ys[50 + t]);
        if (t < 50) wpair(xh, xl, XR_PZWHAT + t, ys[t]);
    }

    // presence: two 565-dots across the block
    float am = 0.0f, as = 0.0f;
    for (int i = t; i < 565; i += 256) {
        float x = ys[i];
        am += x * Wm_pr[i];
        as += x * Ws_pr[i];
    }
    am = warp_sum(am); as = warp_sum(as);
    if (lane == 0) { red[w] = am; red[8 + w] = as; }
    __syncthreads();
    if (t == 0) {
        float m = 0.0f, s = 0.0f;
#pragma unroll
        for (int q = 0; q < 8; q++) { m += red[q]; s += red[8 + q]; }
        float p = sigm(m + bm_pr[0]) * sigm(s + bs_pr[0]);
        zpres_out[(size_t)n * KS + k] = p * zpres_last[(size_t)n * KS + k];
    }
}

// ---------------- host ----------------
extern "C" void kernel_launch(void* const* d_in, const int* in_sizes, int n_in,
                              void* d_out, int out_size) {
    const float* img         = (const float*)d_in[0];
    const float* zwhat_last  = (const float*)d_in[1];
    const float* zwhere_last = (const float*)d_in[2];
    const float* zpres_last  = (const float*)d_in[3];
    const float* hidden_last = (const float*)d_in[4];
    const float* W_loca = (const float*)d_in[5];
    const float* b_loca = (const float*)d_in[6];
    const float* Wg     = (const float*)d_in[7];
    const float* bg     = (const float*)d_in[8];
    const float* Wih_rel = (const float*)d_in[9];
    const float* Whh_rel = (const float*)d_in[10];
    const float* bih_rel = (const float*)d_in[11];
    const float* bhh_rel = (const float*)d_in[12];
    const float* Wih_tem = (const float*)d_in[13];
    const float* Whh_tem = (const float*)d_in[14];
    const float* bih_tem = (const float*)d_in[15];
    const float* bhh_tem = (const float*)d_in[16];
    const float* Wm_wh = (const float*)d_in[17];
    const float* bm_wh = (const float*)d_in[18];
    const float* Wm_wt = (const float*)d_in[21];
    const float* bm_wt = (const float*)d_in[22];
    const float* Wm_pr = (const float*)d_in[25];
    const float* bm_pr = (const float*)d_in[26];
    const float* Ws_pr = (const float*)d_in[27];
    const float* bs_pr = (const float*)d_in[28];

    float* out = (float*)d_out;
    float* zwhat_out  = out;
    float* zwhere_out = out + (size_t)NB * KS * 50;
    float* zpres_out  = zwhere_out + (size_t)NB * KS * 3;
    float* htemp_out  = zpres_out + (size_t)NB * KS * 1;

    void *pG1h, *pG1l, *pXrh, *pXrl, *pXth, *pXtl;
    void *pWr, *pWt, *pWg, *pBrel, *pBtem, *pHr, *pCr;
    cudaGetSymbolAddress(&pG1h, d_G1h); cudaGetSymbolAddress(&pG1l, d_G1l);
    cudaGetSymbolAddress(&pXrh, d_xrh); cudaGetSymbolAddress(&pXrl, d_xrl);
    cudaGetSymbolAddress(&pXth, d_xth); cudaGetSymbolAddress(&pXtl, d_xtl);
    cudaGetSymbolAddress(&pWr, d_Wr); cudaGetSymbolAddress(&pWt, d_Wt);
    cudaGetSymbolAddress(&pWg, d_Wg);
    cudaGetSymbolAddress(&pBrel, d_brel); cudaGetSymbolAddress(&pBtem, d_btem);
    cudaGetSymbolAddress(&pHr, d_hr); cudaGetSymbolAddress(&pCr, d_cr);

    cudaFuncSetAttribute(hmma_gemm<0>, cudaFuncAttributeMaxDynamicSharedMemorySize, SMEM_REQ);
    cudaFuncSetAttribute(hmma_gemm<1>, cudaFuncAttributeMaxDynamicSharedMemorySize, SMEM_REQ);
    cudaFuncSetAttribute(hmma_gemm<2>, cudaFuncAttributeMaxDynamicSharedMemorySize, SMEM_REQ);

    prep_kernel<<<2048, 256>>>(Wih_rel, Whh_rel, bih_rel, bhh_rel,
                               Wih_tem, Whh_tem, bih_tem, bhh_tem, Wg);
    staticpack_kernel<<<NB * KS, 256>>>(img, hidden_last, zwhere_last, zwhat_last,
                                        W_loca, b_loca);
    // enc GEMM: M=16384, N=128(100 real), K=2560, full 2-term -> xrel[:,0:100] hi/lo
    {
        dim3 grid(1, NB * KS / 64);
        hmma_gemm<1><<<grid, 256, SMEM_REQ>>>(
            (const __half*)pG1h, (const __half*)pG1l, KENC,
            (const __half*)pWg, KENC,
            bg, nullptr, nullptr,
            (__half*)pXrh, (__half*)pXrl, KREL,
            KENC, 0, 100, 0);
    }
    for (int k = 0; k < KS; k++) {
        // rel gates GEMM + LSTM epilogue: M=2048 (k-major rows), N=1024, K=768, 2-term
        {
            dim3 grid(NGATE / 128, NB / 64);
            hmma_gemm<0><<<grid, 256, SMEM_REQ>>>(
                (const __half*)pXrh + (size_t)k * NB * KREL,
                (const __half*)pXrl + (size_t)k * NB * KREL, KREL,
                (const __half*)pWr, KREL,
                (const float*)pBrel, (float*)pCr, (float*)pHr,
                nullptr, nullptr, 0, KREL, 0, NGATE, k);
        }
        relglimpse2_kernel<<<NB, 256>>>(img, hidden_last, zwhere_last, zwhat_last,
                                        Wm_wh, bm_wh, zwhat_out, zwhere_out, k);
        // tem gates GEMM + LSTM epilogue: K=3136, single-term for k<2560 (g2 block)
        {
            dim3 grid(NGATE / 128, NB / 64);
            hmma_gemm<2><<<grid, 256, SMEM_REQ>>>(
                (const __half*)pXth, (const __half*)pXtl, KTEM,
                (const __half*)pWt, KTEM,
                (const float*)pBtem, (float*)pCr, htemp_out,
                nullptr, nullptr, 0, KTEM, 2560, NGATE, k);
        }
        head_kernel<<<NB, 256>>>(zwhat_last, zpres_last, Wm_wt, bm_wt,
                                 Wm_pr, bm_pr, Ws_pr, bs_pr,
                                 zwhere_out, zwhat_out, zpres_out, htemp_out, k);
    }
}

// round 13
// speedup vs baseline: 1.5383x; 1.0590x over previous
#include <cuda_runtime.h>
#include <cuda_fp16.h>
#include <cstdint>
#include <math.h>

#define NB   2048
#define KS   8
#define HID  256
#define IMG_HW 16384

#define KENC 2560   // glimpse K padded (2500 real)
#define KREL 768    // rel K padded (718 real)
#define KTEM 3136   // tem K padded (3118 real)
#define NGATE 1024

// xrel col offsets: [enc100|zwl3|pzw3|zwhatl50|pzwhat50|hl256|h_r256]
#define XR_ZWL 100
#define XR_PZW 103
#define XR_ZWHATL 106
#define XR_PZWHAT 156
#define XR_HL  206
#define XR_HR  462
// xtem col offsets: [g2 2500|zw3|pzw3|zwhatl50|pzwhat50|hl256|h_r2 256]
#define XT_ZW 2500
#define XT_PZW 2503
#define XT_ZWHATL 2506
#define XT_PZWHAT 2556
#define XT_HL 2606
#define XT_HR 2862

// ---------------- scratch ----------------
// activations as fp16 (hi, lo) pairs; k-major layout: row = k*NB + n
// (lo arrays retained for a selective-dual fallback via splitK; currently unread)
__device__ __half d_G1h[(size_t)NB * KS * KENC];
__device__ __half d_G1l[(size_t)NB * KS * KENC];
__device__ __half d_xrh[(size_t)NB * KS * KREL];
__device__ __half d_xrl[(size_t)NB * KS * KREL];
__device__ __half d_xth[(size_t)NB * KTEM];
__device__ __half d_xtl[(size_t)NB * KTEM];
__device__ float d_hr[(size_t)NB * HID];
__device__ float d_cr[(size_t)NB * HID];
// weights: single fp16, gate-interleaved rows (row' = unit*4 + gate)
__device__ __half d_Wr[(size_t)NGATE * KREL];
__device__ __half d_Wt[(size_t)NGATE * KTEM];
__device__ __half d_Wg[(size_t)128 * KENC];
__device__ float d_brel[NGATE];
__device__ float d_btem[NGATE];

// ---------------- ptx helpers (sm_80-era, safe for compute_103 PTX) ----------------
__device__ __forceinline__ uint32_t smem_u32(const void* p) {
    uint32_t a;
    asm("{ .reg .u64 t; cvta.to.shared.u64 t, %1; cvt.u32.u64 %0, t; }" : "=r"(a) : "l"(p));
    return a;
}
__device__ __forceinline__ void cp16(uint32_t dst, const void* src) {
    asm volatile("cp.async.ca.shared.global [%0], [%1], 16;" :: "r"(dst), "l"(src));
}
__device__ __forceinline__ void cp_commit() { asm volatile("cp.async.commit_group;"); }
__device__ __forceinline__ void cp_wait3() { asm volatile("cp.async.wait_group 3;"); }
__device__ __forceinline__ void cp_wait2() { asm volatile("cp.async.wait_group 2;"); }
__device__ __forceinline__ void cp_wait1() { asm volatile("cp.async.wait_group 1;"); }
__device__ __forceinline__ void cp_wait0() { asm volatile("cp.async.wait_group 0;"); }
__device__ __forceinline__ void ldm_x4(uint32_t* r, uint32_t a) {
    asm volatile("ldmatrix.sync.aligned.m8n8.x4.shared.b16 {%0,%1,%2,%3}, [%4];"
                 : "=r"(r[0]), "=r"(r[1]), "=r"(r[2]), "=r"(r[3]) : "r"(a));
}
__device__ __forceinline__ void ldm_x2(uint32_t* r, uint32_t a) {
    asm volatile("ldmatrix.sync.aligned.m8n8.x2.shared.b16 {%0,%1}, [%2];"
                 : "=r"(r[0]), "=r"(r[1]) : "r"(a));
}
__device__ __forceinline__ void mma_f16(float* c, const uint32_t* a, const uint32_t* b) {
    asm volatile("mma.sync.aligned.m16n8k16.row.col.f32.f16.f16.f32 "
                 "{%0,%1,%2,%3}, {%4,%5,%6,%7}, {%8,%9}, {%0,%1,%2,%3};"
                 : "+f"(c[0]), "+f"(c[1]), "+f"(c[2]), "+f"(c[3])
                 : "r"(a[0]), "r"(a[1]), "r"(a[2]), "r"(a[3]), "r"(b[0]), "r"(b[1]));
}

// ---------------- math helpers ----------------
__device__ __forceinline__ float sigm(float x) { return 1.0f / (1.0f + expf(-x)); }
__device__ __forceinline__ float warp_sum(float v) {
#pragma unroll
    for (int o = 16; o; o >>= 1) v += __shfl_xor_sync(0xffffffffu, v, o);
    return v;
}
// split fp32 -> fp16 hi + fp16 lo
__device__ __forceinline__ void wpair(__half* ph, __half* pl, int i, float x) {
    __half h = __float2half(x);
    ph[i] = h;
    pl[i] = __float2half(x - __half2float(h));
}
__device__ __forceinline__ float samp(const float* __restrict__ im, int y, int x) {
    if ((unsigned)y < 128u && (unsigned)x < 128u) return im[(y << 7) + x];
    return 0.0f;
}
__device__ __forceinline__ float bilin(const float* __restrict__ imgN,
                                       float s, float tx, float ty, int g) {
    int iy = g / 50, ix = g - iy * 50;
    float gx = -1.0f + (float)ix * (2.0f / 49.0f);
    float gy = -1.0f + (float)iy * (2.0f / 49.0f);
    float px = (s * gx + tx + 1.0f) * 0.5f * 127.0f;
    float py = (s * gy + ty + 1.0f) * 0.5f * 127.0f;
    float x0f = floorf(px), y0f = floorf(py);
    float wx1 = px - x0f, wy1 = py - y0f;
    int x0 = (int)x0f, y0 = (int)y0f;
    float v00 = samp(imgN, y0, x0),     v01 = samp(imgN, y0, x0 + 1);
    float v10 = samp(imgN, y0 + 1, x0), v11 = samp(imgN, y0 + 1, x0 + 1);
    return (1.0f - wy1) * (1.0f - wx1) * v00 + (1.0f - wy1) * wx1 * v01
         + wy1 * (1.0f - wx1) * v10 + wy1 * wx1 * v11;
}
// hi-only glimpse (GEMMs consume the glimpse blocks single-term)
__device__ __forceinline__ void glimpse_hi(const float* __restrict__ imgN,
                                           float s, float tx, float ty,
                                           __half* __restrict__ dh, int t) {
    for (int g = t; g < 2500; g += 256) {
        dh[g] = __float2half(bilin(imgN, s, tx, ty, g));
    }
}

// ---------------- prep ----------------
__global__ void prep_kernel(const float* __restrict__ Wih_rel, const float* __restrict__ Whh_rel,
                            const float* __restrict__ bih_rel, const float* __restrict__ bhh_rel,
                            const float* __restrict__ Wih_tem, const float* __restrict__ Whh_tem,
                            const float* __restrict__ bih_tem, const float* __restrict__ bhh_tem,
                            const float* __restrict__ Wg) {
    int tid = blockIdx.x * blockDim.x + threadIdx.x;
    int nt = gridDim.x * blockDim.x;
    // gate-interleaved: out row r' -> unit u=r'>>2, gate g=r'&3, orig row = g*256+u
    for (int i = tid; i < NGATE * KREL; i += nt) {
        int rp = i / KREL, c = i - rp * KREL;
        int orig = (rp & 3) * 256 + (rp >> 2);
        float v = 0.0f;
        if (c < 462) v = Wih_rel[orig * 462 + c];
        else if (c < 718) v = Whh_rel[orig * 256 + (c - 462)];
        d_Wr[i] = __float2half(v);
    }
    for (int i = tid; i < NGATE * KTEM; i += nt) {
        int rp = i / KTEM, c = i - rp * KTEM;
        int orig = (rp & 3) * 256 + (rp >> 2);
        float v = 0.0f;
        if (c < 2862) v = Wih_tem[orig * 2862 + c];
        else if (c < 3118) v = Whh_tem[orig * 256 + (c - 2862)];
        d_Wt[i] = __float2half(v);
    }
    for (int i = tid; i < 128 * KENC; i += nt) {
        int r = i / KENC, c = i - r * KENC;
        float v = (r < 100 && c < 2500) ? Wg[r * 2500 + c] : 0.0f;
        d_Wg[i] = __float2half(v);
    }
    for (int i = tid; i < NGATE; i += nt) {
        int orig = (i & 3) * 256 + (i >> 2);
        d_brel[i] = bih_rel[orig] + bhh_rel[orig];
        d_btem[i] = bih_tem[orig] + bhh_tem[orig];
    }
    for (int i = tid; i < NB * HID; i += nt) { d_hr[i] = 0.0f; d_cr[i] = 0.0f; }
    // zero recurrent xrel cols for k=0 rows (rows 0..NB-1)
    __half z = __float2half(0.0f);
    for (int i = tid; i < NB * 3; i += nt) {
        int r = i / 3, c = XR_PZW + i % 3;
        d_xrh[(size_t)r * KREL + c] = z; d_xrl[(size_t)r * KREL + c] = z;
    }
    for (int i = tid; i < NB * 50; i += nt) {
        int r = i / 50, c = XR_PZWHAT + i % 50;
        d_xrh[(size_t)r * KREL + c] = z; d_xrl[(size_t)r * KREL + c] = z;
    }
    for (int i = tid; i < NB * HID; i += nt) {
        int r = i / HID, c = XR_HR + i % HID;
        d_xrh[(size_t)r * KREL + c] = z; d_xrl[(size_t)r * KREL + c] = z;
    }
    // pads
    for (int i = tid; i < NB * KS * 60; i += nt) {
        int r = i / 60, c = 2500 + i % 60;
        d_G1h[(size_t)r * KENC + c] = z; d_G1l[(size_t)r * KENC + c] = z;
    }
    for (int i = tid; i < NB * KS * 50; i += nt) {
        int r = i / 50, c = 718 + i % 50;
        d_xrh[(size_t)r * KREL + c] = z; d_xrl[(size_t)r * KREL + c] = z;
    }
    for (int i = tid; i < NB * 18; i += nt) {
        int r = i / 18, c = 3118 + i % 18;
        d_xth[(size_t)r * KTEM + c] = z; d_xtl[(size_t)r * KTEM + c] = z;
    }
    // zero xtl in the g2 region (never rewritten; safe if split boundary changes)
    for (size_t i = tid; i < (size_t)NB * XT_ZW; i += nt) {
        size_t r = i / XT_ZW, c = i % XT_ZW;
        d_xtl[r * KTEM + c] = z;
    }
}

// ---------------- static pack: zwb + glimpse1 + static xrel cols, all (n,k) ----------------
__global__ __launch_bounds__(256) void staticpack_kernel(
    const float* __restrict__ img, const float* __restrict__ hidden_last,
    const float* __restrict__ zwhere_last, const float* __restrict__ zwhat_last,
    const float* __restrict__ W_loca, const float* __restrict__ b_loca) {
    int row = blockIdx.x, t = threadIdx.x;   // row = k*NB + n
    int k = row / NB, n = row - k * NB;
    size_t inrow = (size_t)n * KS + k;
    __shared__ float sred[3][8];
    __shared__ float szw[3];
    int w = t >> 5, lane = t & 31;

    float h = hidden_last[inrow * HID + t];
    float p0 = h * W_loca[t];
    float p1 = h * W_loca[HID + t];
    float p2 = h * W_loca[2 * HID + t];
    p0 = warp_sum(p0); p1 = warp_sum(p1); p2 = warp_sum(p2);
    if (lane == 0) { sred[0][w] = p0; sred[1][w] = p1; sred[2][w] = p2; }

    __half* xh = d_xrh + (size_t)row * KREL;
    __half* xl = d_xrl + (size_t)row * KREL;
    wpair(xh, xl, XR_HL + t, h);
    if (t < 3)  wpair(xh, xl, XR_ZWL + t, zwhere_last[inrow * 3 + t]);
    if (t < 50) wpair(xh, xl, XR_ZWHATL + t, zwhat_last[inrow * 50 + t]);
    __syncthreads();
    if (t < 3) {
        float s = 0.0f;
#pragma unroll
        for (int q = 0; q < 8; q++) s += sred[t][q];
        s += b_loca[t];
        szw[t] = fmaxf(s, 0.0f) + zwhere_last[inrow * 3 + t];
    }
    __syncthreads();
    glimpse_hi(img + (size_t)n * IMG_HW, szw[0], szw[1], szw[2],
               d_G1h + (size_t)row * KENC, t);
}

// ---------------- HMMA fp16 GEMM with asymmetric split (splitK=K -> all single) ----
// CTA 64x128 (MxN), BK=32, 4-stage cp.async, 2 CTAs/SM.
// A split (hi,lo) fp16; B single fp16. Chunks with k0 < splitK use ONLY the hi
// term (1 MMA per k16); chunks with k0 >= splitK use hi+lo (2 MMAs).
// smem rows stride 80B (gcd(5,8)=1 -> ldmatrix conflict-free).
// Stage: Ah(64r) | Al(64r) | B(128r) = 256 rows * 80B = 20480B
// EPI 0: rel LSTM pointwise (write d_cr, d_hr)
// EPI 1: relu -> (hi,lo) fp16 out (enc)
// EPI 2: tem LSTM pointwise (read d_cr, write htemp_out)
#define ROW_B 80
#define OFF_AL (64 * ROW_B)          // 5120
#define OFF_B  (128 * ROW_B)         // 10240
#define STAGE_B (256 * ROW_B)        // 20480
#define SMEM_REQ (4 * STAGE_B)       // 81920

template <int EPI>
__global__ __launch_bounds__(256, 2) void hmma_gemm(
    const __half* __restrict__ Ah, const __half* __restrict__ Al, int lda,
    const __half* __restrict__ B, int ldb,
    const float* __restrict__ bias,
    float* __restrict__ cstate, float* __restrict__ hout,
    __half* __restrict__ Chi, __half* __restrict__ Clo,
    int ldc, int K, int splitK, int nReal, int kk) {
    extern __shared__ char smem[];
    const uint32_t sb = smem_u32(smem);
    const int tid = threadIdx.x;
    const int lane = tid & 31, wid = tid >> 5;
    const int wm = wid >> 2, wn = wid & 3;      // 2 x 4 warp grid; warp tile 32x32
    const int bm = blockIdx.y * 64, bn = blockIdx.x * 128;
    const int nK = K / 32;

    float acc[2][4][4];
#pragma unroll
    for (int i = 0; i < 2; i++)
#pragma unroll
        for (int j = 0; j < 4; j++)
#pragma unroll
            for (int q = 0; q < 4; q++) acc[i][j][q] = 0.0f;

    auto load_stage = [&](int st, int kt) {
        int k0 = kt * 32;
        bool dual = (k0 >= splitK);
        uint32_t base = sb + st * STAGE_B;
        // 256 rows * 4 chunks of 16B; skip Al rows (64..127) for single-term chunks
#pragma unroll
        for (int q = 0; q < 4; q++) {
            int idx = q * 256 + tid;          // 0..1023
            int row = idx >> 2;               // 0..255
            int ch = idx & 3;                 // 0..3
            const __half* gp;
            if (row < 64)       gp = Ah + (size_t)(bm + row) * lda + k0 + ch * 8;
            else if (row < 128) {
                if (!dual) continue;
                gp = Al + (size_t)(bm + row - 64) * lda + k0 + ch * 8;
            }
            else                gp = B + (size_t)(bn + row - 128) * ldb + k0 + ch * 8;
            cp16(base + row * ROW_B + ch * 16, gp);
        }
        cp_commit();
    };

    load_stage(0, 0);
    if (nK > 1) load_stage(1, 1);
    if (nK > 2) load_stage(2, 2);
    int st = 0;
    for (int kt = 0; kt < nK; kt++) {
        if (kt + 3 < nK) { load_stage((kt + 3) & 3, kt + 3); cp_wait3(); }
        else if (kt + 2 < nK) cp_wait2();
        else if (kt + 1 < nK) cp_wait1();
        else cp_wait0();
        __syncthreads();
        uint32_t base = sb + st * STAGE_B;
        st = (st + 1) & 3;
        bool dual = (kt * 32 >= splitK);
#pragma unroll
        for (int ks = 0; ks < 2; ks++) {
            uint32_t ah[2][4], al[2][4], bh[4][2];
#pragma unroll
            for (int mf = 0; mf < 2; mf++) {
                int row = wm * 32 + mf * 16 + (lane & 15);
                int ch = ks * 2 + (lane >> 4);
                uint32_t a = base + row * ROW_B + ch * 16;
                ldm_x4(ah[mf], a);
                if (dual) ldm_x4(al[mf], a + OFF_AL);
            }
#pragma unroll
            for (int nf = 0; nf < 4; nf++) {
                int row = wn * 32 + nf * 8 + (lane & 7);
                int ch = ks * 2 + ((lane >> 3) & 1);
                ldm_x2(bh[nf], base + OFF_B + row * ROW_B + ch * 16);
            }
#pragma unroll
            for (int mf = 0; mf < 2; mf++)
#pragma unroll
                for (int nf = 0; nf < 4; nf++) {
                    mma_f16(acc[mf][nf], ah[mf], bh[nf]);
                    if (dual) mma_f16(acc[mf][nf], al[mf], bh[nf]);
                }
        }
        __syncthreads();
    }

    // epilogue
    int trow = lane >> 2, tcol2 = (lane & 3) * 2;
    bool evn = ((lane & 1) == 0);   // holds (i,f); odd holds (g,o)
#pragma unroll
    for (int mf = 0; mf < 2; mf++) {
        int r0 = bm + wm * 32 + mf * 16 + trow;
#pragma unroll
        for (int nf = 0; nf < 4; nf++) {
            int col = bn + wn * 32 + nf * 8 + tcol2;
            if (EPI == 1) {
#pragma unroll
                for (int e = 0; e < 4; e++) {
                    int cc = col + (e & 1);
                    int rr = r0 + (e >> 1) * 8;
                    if (cc < nReal) {
                        float v = fmaxf(acc[mf][nf][e] + bias[cc], 0.0f);
                        wpair(Chi + (size_t)rr * ldc, Clo + (size_t)rr * ldc, cc, v);
                    }
                }
            } else {
                int u = col >> 2;  // hidden unit
                float b0 = bias[col], b1 = bias[col + 1];
                float x0 = acc[mf][nf][0] + b0, x1 = acc[mf][nf][1] + b1;
                float x2 = acc[mf][nf][2] + b0, x3 = acc[mf][nf][3] + b1;
                float vA0, vB0, vA1, vB1;
                if (evn) { vA0 = sigm(x0); vB0 = sigm(x1); vA1 = sigm(x2); vB1 = sigm(x3); }
                else     { vA0 = tanhf(x0); vB0 = sigm(x1); vA1 = tanhf(x2); vB1 = sigm(x3); }
                // exchange: even receives tanh(g); odd receives sigm(i) (unused)
                float tA0 = __shfl_xor_sync(0xffffffffu, vA0, 1);
                float tA1 = __shfl_xor_sync(0xffffffffu, vA1, 1);
                float c20 = 0.0f, c21 = 0.0f;
                if (evn) {
                    float co0 = cstate[(size_t)r0 * HID + u];
                    float co1 = cstate[(size_t)(r0 + 8) * HID + u];
                    c20 = vB0 * co0 + vA0 * tA0;
                    c21 = vB1 * co1 + vA1 * tA1;
                    if (EPI == 0) {
                        cstate[(size_t)r0 * HID + u] = c20;
                        cstate[(size_t)(r0 + 8) * HID + u] = c21;
                    }
                }
                float cr0 = __shfl_xor_sync(0xffffffffu, c20, 1);
                float cr1 = __shfl_xor_sync(0xffffffffu, c21, 1);
                if (!evn) {
                    float h0 = vB0 * tanhf(cr0);
                    float h1 = vB1 * tanhf(cr1);
                    if (EPI == 0) {
                        hout[(size_t)r0 * HID + u] = h0;
                        hout[(size_t)(r0 + 8) * HID + u] = h1;
                    } else {   // EPI == 2: write h_t to output [n, k, HID]
                        hout[((size_t)r0 * KS + kk) * HID + u] = h0;
                        hout[((size_t)(r0 + 8) * KS + kk) * HID + u] = h1;
                    }
                }
            }
        }
    }
}

// ---------------- rel stage 2: zw linear + glimpse2 + xtem pack ----------------
__global__ __launch_bounds__(256) void relglimpse2_kernel(
    const float* __restrict__ img, const float* __restrict__ hidden_last,
    const float* __restrict__ zwhere_last, const float* __restrict__ zwhat_last,
    const float* __restrict__ Wm_wh, const float* __restrict__ bm_wh,
    const float* __restrict__ zwhat_out, float* __restrict__ zwhere_out, int k) {
    int n = blockIdx.x, t = threadIdx.x;
    __shared__ float hs[HID];
    __shared__ float sred[3][8];
    __shared__ float szw[3];
    int w = t >> 5, lane = t & 31;

    float h = d_hr[n * HID + t];    // h_r2 from rel GEMM epilogue
    hs[t] = h;

    __half* xh = d_xth + (size_t)n * KTEM;
    __half* xl = d_xtl + (size_t)n * KTEM;
    wpair(xh, xl, XT_HR + t, h);
    wpair(xh, xl, XT_HL + t, hidden_last[((size_t)n * KS + k) * HID + t]);
    if (t < 3) wpair(xh, xl, XT_PZW + t, k ? zwhere_out[((size_t)n * KS + k - 1) * 3 + t] : 0.0f);
    if (t < 50) {
        wpair(xh, xl, XT_ZWHATL + t, zwhat_last[((size_t)n * KS + k) * 50 + t]);
        wpair(xh, xl, XT_PZWHAT + t, k ? zwhat_out[((size_t)n * KS + k - 1) * 50 + t] : 0.0f);
    }
    __syncthreads();

    // zw = [zwl(3), h_r2(256)] @ Wm_wh^T + bm_wh (K=259)
    float c0 = (t < 3) ? zwhere_last[((size_t)n * KS + k) * 3 + t] : hs[t - 3];
    float q0 = c0 * Wm_wh[t];
    float q1 = c0 * Wm_wh[259 + t];
    float q2 = c0 * Wm_wh[518 + t];
    if (t < 3) {
        float c1 = hs[253 + t];
        q0 += c1 * Wm_wh[256 + t];
        q1 += c1 * Wm_wh[259 + 256 + t];
        q2 += c1 * Wm_wh[518 + 256 + t];
    }
    q0 = warp_sum(q0); q1 = warp_sum(q1); q2 = warp_sum(q2);
    if (lane == 0) { sred[0][w] = q0; sred[1][w] = q1; sred[2][w] = q2; }
    __syncthreads();
    if (t < 3) {
        float s = 0.0f;
#pragma unroll
        for (int q = 0; q < 8; q++) s += sred[t][q];
        s += bm_wh[t];
        szw[t] = s;
        zwhere_out[((size_t)n * KS + k) * 3 + t] = s;
        wpair(xh, xl, XT_ZW + t, s);
    }
    __syncthreads();
    // g2 block is consumed single-term by the tem GEMM -> write hi only
    glimpse_hi(img + (size_t)n * IMG_HW, szw[0], szw[1], szw[2], xh, t);
}

// ---------------- head: zwhat GEMV + presence + fused recpack for step k+1 ----------------
__global__ __launch_bounds__(256) void head_kernel(
    const float* __restrict__ zwhat_last, const float* __restrict__ zpres_last,
    const float* __restrict__ Wm_wt, const float* __restrict__ bm_wt,
    const float* __restrict__ Wm_pr, const float* __restrict__ bm_pr,
    const float* __restrict__ Ws_pr, const float* __restrict__ bs_pr,
    const float* __restrict__ zwhere_out, float* __restrict__ zwhat_out,
    float* __restrict__ zpres_out, const float* __restrict__ htemp_out, int k) {
    int n = blockIdx.x, t = threadIdx.x;
    __shared__ float xs[562];
    __shared__ float ys[565];
    __shared__ float red[16];
    int w = t >> 5, lane = t & 31;

    float ht = htemp_out[((size_t)n * KS + k) * HID + t];  // from tem GEMM epilogue
    float hr = d_hr[n * HID + t];
    xs[50 + t] = hr; xs[306 + t] = ht;
    ys[53 + t] = hr; ys[309 + t] = ht;
    if (t < 50) xs[t] = zwhat_last[((size_t)n * KS + k) * 50 + t];
    if (t < 3) ys[50 + t] = zwhere_out[((size_t)n * KS + k) * 3 + t];
    __syncthreads();

    for (int j = w; j < 50; j += 8) {
        const float* wr = Wm_wt + (size_t)j * 562;
        float acc = 0.0f;
        for (int i = lane; i < 562; i += 32) acc += xs[i] * wr[i];
        acc = warp_sum(acc);
        if (lane == 0) {
            float z = acc + bm_wt[j];
            ys[j] = z;
            zwhat_out[((size_t)n * KS + k) * 50 + j] = z;
        }
    }
    __syncthreads();

    // fused recpack for step k+1 (k-major xrel rows (k+1)*NB + n)
    if (k < KS - 1) {
        size_t row = (size_t)(k + 1) * NB + n;
        __half* xh = d_xrh + row * KREL;
        __half* xl = d_xrl + row * KREL;
        wpair(xh, xl, XR_HR + t, hr);
        if (t < 3)  wpair(xh, xl, XR_PZW + t, ys[50 + t]);
        if (t < 50) wpair(xh, xl, XR_PZWHAT + t, ys[t]);
    }

    // presence: two 565-dots across the block
    float am = 0.0f, as = 0.0f;
    for (int i = t; i < 565; i += 256) {
        float x = ys[i];
        am += x * Wm_pr[i];
        as += x * Ws_pr[i];
    }
    am = warp_sum(am); as = warp_sum(as);
    if (lane == 0) { red[w] = am; red[8 + w] = as; }
    __syncthreads();
    if (t == 0) {
        float m = 0.0f, s = 0.0f;
#pragma unroll
        for (int q = 0; q < 8; q++) { m += red[q]; s += red[8 + q]; }
        float p = sigm(m + bm_pr[0]) * sigm(s + bs_pr[0]);
        zpres_out[(size_t)n * KS + k] = p * zpres_last[(size_t)n * KS + k];
    }
}

// ---------------- host ----------------
extern "C" void kernel_launch(void* const* d_in, const int* in_sizes, int n_in,
                              void* d_out, int out_size) {
    const float* img         = (const float*)d_in[0];
    const float* zwhat_last  = (const float*)d_in[1];
    const float* zwhere_last = (const float*)d_in[2];
    const float* zpres_last  = (const float*)d_in[3];
    const float* hidden_last = (const float*)d_in[4];
    const float* W_loca = (const float*)d_in[5];
    const float* b_loca = (const float*)d_in[6];
    const float* Wg     = (const float*)d_in[7];
    const float* bg     = (const float*)d_in[8];
    const float* Wih_rel = (const float*)d_in[9];
    const float* Whh_rel = (const float*)d_in[10];
    const float* bih_rel = (const float*)d_in[11];
    const float* bhh_rel = (const float*)d_in[12];
    const float* Wih_tem = (const float*)d_in[13];
    const float* Whh_tem = (const float*)d_in[14];
    const float* bih_tem = (const float*)d_in[15];
    const float* bhh_tem = (const float*)d_in[16];
    const float* Wm_wh = (const float*)d_in[17];
    const float* bm_wh = (const float*)d_in[18];
    const float* Wm_wt = (const float*)d_in[21];
    const float* bm_wt = (const float*)d_in[22];
    const float* Wm_pr = (const float*)d_in[25];
    const float* bm_pr = (const float*)d_in[26];
    const float* Ws_pr = (const float*)d_in[27];
    const float* bs_pr = (const float*)d_in[28];

    float* out = (float*)d_out;
    float* zwhat_out  = out;
    float* zwhere_out = out + (size_t)NB * KS * 50;
    float* zpres_out  = zwhere_out + (size_t)NB * KS * 3;
    float* htemp_out  = zpres_out + (size_t)NB * KS * 1;

    void *pG1h, *pG1l, *pXrh, *pXrl, *pXth, *pXtl;
    void *pWr, *pWt, *pWg, *pBrel, *pBtem, *pHr, *pCr;
    cudaGetSymbolAddress(&pG1h, d_G1h); cudaGetSymbolAddress(&pG1l, d_G1l);
    cudaGetSymbolAddress(&pXrh, d_xrh); cudaGetSymbolAddress(&pXrl, d_xrl);
    cudaGetSymbolAddress(&pXth, d_xth); cudaGetSymbolAddress(&pXtl, d_xtl);
    cudaGetSymbolAddress(&pWr, d_Wr); cudaGetSymbolAddress(&pWt, d_Wt);
    cudaGetSymbolAddress(&pWg, d_Wg);
    cudaGetSymbolAddress(&pBrel, d_brel); cudaGetSymbolAddress(&pBtem, d_btem);
    cudaGetSymbolAddress(&pHr, d_hr); cudaGetSymbolAddress(&pCr, d_cr);

    cudaFuncSetAttribute(hmma_gemm<0>, cudaFuncAttributeMaxDynamicSharedMemorySize, SMEM_REQ);
    cudaFuncSetAttribute(hmma_gemm<1>, cudaFuncAttributeMaxDynamicSharedMemorySize, SMEM_REQ);
    cudaFuncSetAttribute(hmma_gemm<2>, cudaFuncAttributeMaxDynamicSharedMemorySize, SMEM_REQ);

    prep_kernel<<<2048, 256>>>(Wih_rel, Whh_rel, bih_rel, bhh_rel,
                               Wih_tem, Whh_tem, bih_tem, bhh_tem, Wg);
    staticpack_kernel<<<NB * KS, 256>>>(img, hidden_last, zwhere_last, zwhat_last,
                                        W_loca, b_loca);
    // enc GEMM: M=16384, N=128(100 real), K=2560, ALL single-term
    {
        dim3 grid(1, NB * KS / 64);
        hmma_gemm<1><<<grid, 256, SMEM_REQ>>>(
            (const __half*)pG1h, (const __half*)pG1l, KENC,
            (const __half*)pWg, KENC,
            bg, nullptr, nullptr,
            (__half*)pXrh, (__half*)pXrl, KREL,
            KENC, KENC, 100, 0);
    }
    for (int k = 0; k < KS; k++) {
        // rel gates GEMM + LSTM epilogue: M=2048 (k-major rows), N=1024, K=768, single
        {
            dim3 grid(NGATE / 128, NB / 64);
            hmma_gemm<0><<<grid, 256, SMEM_REQ>>>(
                (const __half*)pXrh + (size_t)k * NB * KREL,
                (const __half*)pXrl + (size_t)k * NB * KREL, KREL,
                (const __half*)pWr, KREL,
                (const float*)pBrel, (float*)pCr, (float*)pHr,
                nullptr, nullptr, 0, KREL, KREL, NGATE, k);
        }
        relglimpse2_kernel<<<NB, 256>>>(img, hidden_last, zwhere_last, zwhat_last,
                                        Wm_wh, bm_wh, zwhat_out, zwhere_out, k);
        // tem gates GEMM + LSTM epilogue: K=3136, ALL single-term
        {
            dim3 grid(NGATE / 128, NB / 64);
            hmma_gemm<2><<<grid, 256, SMEM_REQ>>>(
                (const __half*)pXth, (const __half*)pXtl, KTEM,
                (const __half*)pWt, KTEM,
                (const float*)pBtem, (float*)pCr, htemp_out,
                nullptr, nullptr, 0, KTEM, KTEM, NGATE, k);
        }
        head_kernel<<<NB, 256>>>(zwhat_last, zpres_last, Wm_wt, bm_wt,
                                 Wm_pr, bm_pr, Ws_pr, bs_pr,
                                 zwhere_out, zwhat_out, zpres_out, htemp_out, k);
    }
}

// round 14
// speedup vs baseline: 1.8302x; 1.1897x over previous
#include <cuda_runtime.h>
#include <cuda_fp16.h>
#include <cstdint>
#include <math.h>

#define NB   2048
#define KS   8
#define HID  256
#define IMG_HW 16384

#define KENC 2560   // glimpse K padded (2500 real)
#define KREL 768    // rel K padded (718 real)
#define KTEM 3136   // tem K padded (3118 real)
#define NGATE 1024

// xrel col offsets: [enc100|zwl3|pzw3|zwhatl50|pzwhat50|hl256|h_r256]
#define XR_ZWL 100
#define XR_PZW 103
#define XR_ZWHATL 106
#define XR_PZWHAT 156
#define XR_HL  206
#define XR_HR  462
// xtem col offsets: [g2 2500|zw3|pzw3|zwhatl50|pzwhat50|hl256|h_r2 256]
#define XT_ZW 2500
#define XT_PZW 2503
#define XT_ZWHATL 2506
#define XT_PZWHAT 2556
#define XT_HL 2606
#define XT_HR 2862

// ---------------- scratch ----------------
// fp16 activations, hi only (single-term GEMMs); k-major layout: row = k*NB + n
__device__ __half d_G1h[(size_t)NB * KS * KENC];
__device__ __half d_xrh[(size_t)NB * KS * KREL];
__device__ __half d_xth[(size_t)NB * KTEM];
__device__ float d_hr[(size_t)NB * HID];
__device__ float d_cr[(size_t)NB * HID];
// weights: single fp16, gate-interleaved rows (row' = unit*4 + gate)
__device__ __half d_Wr[(size_t)NGATE * KREL];
__device__ __half d_Wt[(size_t)NGATE * KTEM];
__device__ __half d_Wg[(size_t)128 * KENC];
__device__ float d_brel[NGATE];
__device__ float d_btem[NGATE];

// ---------------- ptx helpers (sm_80-era, safe for compute_103 PTX) ----------------
__device__ __forceinline__ uint32_t smem_u32(const void* p) {
    uint32_t a;
    asm("{ .reg .u64 t; cvta.to.shared.u64 t, %1; cvt.u32.u64 %0, t; }" : "=r"(a) : "l"(p));
    return a;
}
__device__ __forceinline__ void cp16(uint32_t dst, const void* src) {
    asm volatile("cp.async.ca.shared.global [%0], [%1], 16;" :: "r"(dst), "l"(src));
}
__device__ __forceinline__ void cp_commit() { asm volatile("cp.async.commit_group;"); }
__device__ __forceinline__ void cp_wait3() { asm volatile("cp.async.wait_group 3;"); }
__device__ __forceinline__ void cp_wait2() { asm volatile("cp.async.wait_group 2;"); }
__device__ __forceinline__ void cp_wait1() { asm volatile("cp.async.wait_group 1;"); }
__device__ __forceinline__ void cp_wait0() { asm volatile("cp.async.wait_group 0;"); }
__device__ __forceinline__ void ldm_x4(uint32_t* r, uint32_t a) {
    asm volatile("ldmatrix.sync.aligned.m8n8.x4.shared.b16 {%0,%1,%2,%3}, [%4];"
                 : "=r"(r[0]), "=r"(r[1]), "=r"(r[2]), "=r"(r[3]) : "r"(a));
}
__device__ __forceinline__ void ldm_x2(uint32_t* r, uint32_t a) {
    asm volatile("ldmatrix.sync.aligned.m8n8.x2.shared.b16 {%0,%1}, [%2];"
                 : "=r"(r[0]), "=r"(r[1]) : "r"(a));
}
__device__ __forceinline__ void mma_f16(float* c, const uint32_t* a, const uint32_t* b) {
    asm volatile("mma.sync.aligned.m16n8k16.row.col.f32.f16.f16.f32 "
                 "{%0,%1,%2,%3}, {%4,%5,%6,%7}, {%8,%9}, {%0,%1,%2,%3};"
                 : "+f"(c[0]), "+f"(c[1]), "+f"(c[2]), "+f"(c[3])
                 : "r"(a[0]), "r"(a[1]), "r"(a[2]), "r"(a[3]), "r"(b[0]), "r"(b[1]));
}

// ---------------- math helpers ----------------
__device__ __forceinline__ float sigm(float x) { return 1.0f / (1.0f + expf(-x)); }
__device__ __forceinline__ float warp_sum(float v) {
#pragma unroll
    for (int o = 16; o; o >>= 1) v += __shfl_xor_sync(0xffffffffu, v, o);
    return v;
}
__device__ __forceinline__ float samp(const float* __restrict__ im, int y, int x) {
    if ((unsigned)y < 128u && (unsigned)x < 128u) return im[(y << 7) + x];
    return 0.0f;
}
__device__ __forceinline__ float bilin(const float* __restrict__ imgN,
                                       float s, float tx, float ty, int g) {
    int iy = g / 50, ix = g - iy * 50;
    float gx = -1.0f + (float)ix * (2.0f / 49.0f);
    float gy = -1.0f + (float)iy * (2.0f / 49.0f);
    float px = (s * gx + tx + 1.0f) * 0.5f * 127.0f;
    float py = (s * gy + ty + 1.0f) * 0.5f * 127.0f;
    float x0f = floorf(px), y0f = floorf(py);
    float wx1 = px - x0f, wy1 = py - y0f;
    int x0 = (int)x0f, y0 = (int)y0f;
    float v00 = samp(imgN, y0, x0),     v01 = samp(imgN, y0, x0 + 1);
    float v10 = samp(imgN, y0 + 1, x0), v11 = samp(imgN, y0 + 1, x0 + 1);
    return (1.0f - wy1) * (1.0f - wx1) * v00 + (1.0f - wy1) * wx1 * v01
         + wy1 * (1.0f - wx1) * v10 + wy1 * wx1 * v11;
}
__device__ __forceinline__ void glimpse_hi(const float* __restrict__ imgN,
                                           float s, float tx, float ty,
                                           __half* __restrict__ dh, int t) {
    for (int g = t; g < 2500; g += 256) {
        dh[g] = __float2half(bilin(imgN, s, tx, ty, g));
    }
}

// ---------------- prep ----------------
__global__ void prep_kernel(const float* __restrict__ Wih_rel, const float* __restrict__ Whh_rel,
                            const float* __restrict__ bih_rel, const float* __restrict__ bhh_rel,
                            const float* __restrict__ Wih_tem, const float* __restrict__ Whh_tem,
                            const float* __restrict__ bih_tem, const float* __restrict__ bhh_tem,
                            const float* __restrict__ Wg) {
    int tid = blockIdx.x * blockDim.x + threadIdx.x;
    int nt = gridDim.x * blockDim.x;
    // gate-interleaved: out row r' -> unit u=r'>>2, gate g=r'&3, orig row = g*256+u
    for (int i = tid; i < NGATE * KREL; i += nt) {
        int rp = i / KREL, c = i - rp * KREL;
        int orig = (rp & 3) * 256 + (rp >> 2);
        float v = 0.0f;
        if (c < 462) v = Wih_rel[orig * 462 + c];
        else if (c < 718) v = Whh_rel[orig * 256 + (c - 462)];
        d_Wr[i] = __float2half(v);
    }
    for (int i = tid; i < NGATE * KTEM; i += nt) {
        int rp = i / KTEM, c = i - rp * KTEM;
        int orig = (rp & 3) * 256 + (rp >> 2);
        float v = 0.0f;
        if (c < 2862) v = Wih_tem[orig * 2862 + c];
        else if (c < 3118) v = Whh_tem[orig * 256 + (c - 2862)];
        d_Wt[i] = __float2half(v);
    }
    for (int i = tid; i < 128 * KENC; i += nt) {
        int r = i / KENC, c = i - r * KENC;
        float v = (r < 100 && c < 2500) ? Wg[r * 2500 + c] : 0.0f;
        d_Wg[i] = __float2half(v);
    }
    for (int i = tid; i < NGATE; i += nt) {
        int orig = (i & 3) * 256 + (i >> 2);
        d_brel[i] = bih_rel[orig] + bhh_rel[orig];
        d_btem[i] = bih_tem[orig] + bhh_tem[orig];
    }
    for (int i = tid; i < NB * HID; i += nt) { d_hr[i] = 0.0f; d_cr[i] = 0.0f; }
    __half z = __float2half(0.0f);
    // zero recurrent xrel cols for k=0 rows
    for (int i = tid; i < NB * 3; i += nt) {
        int r = i / 3, c = XR_PZW + i % 3;
        d_xrh[(size_t)r * KREL + c] = z;
    }
    for (int i = tid; i < NB * 50; i += nt) {
        int r = i / 50, c = XR_PZWHAT + i % 50;
        d_xrh[(size_t)r * KREL + c] = z;
    }
    for (int i = tid; i < NB * HID; i += nt) {
        int r = i / HID, c = XR_HR + i % HID;
        d_xrh[(size_t)r * KREL + c] = z;
    }
    // pads
    for (int i = tid; i < NB * KS * 60; i += nt) {
        int r = i / 60, c = 2500 + i % 60;
        d_G1h[(size_t)r * KENC + c] = z;
    }
    for (int i = tid; i < NB * KS * 50; i += nt) {
        int r = i / 50, c = 718 + i % 50;
        d_xrh[(size_t)r * KREL + c] = z;
    }
    for (int i = tid; i < NB * 18; i += nt) {
        int r = i / 18, c = 3118 + i % 18;
        d_xth[(size_t)r * KTEM + c] = z;
    }
}

// ---------------- static pack: zwb + glimpse1 + static xrel cols, all (n,k) ----------------
__global__ __launch_bounds__(256) void staticpack_kernel(
    const float* __restrict__ img, const float* __restrict__ hidden_last,
    const float* __restrict__ zwhere_last, const float* __restrict__ zwhat_last,
    const float* __restrict__ W_loca, const float* __restrict__ b_loca) {
    int row = blockIdx.x, t = threadIdx.x;   // row = k*NB + n
    int k = row / NB, n = row - k * NB;
    size_t inrow = (size_t)n * KS + k;
    __shared__ float sred[3][8];
    __shared__ float szw[3];
    int w = t >> 5, lane = t & 31;

    float h = hidden_last[inrow * HID + t];
    float p0 = h * W_loca[t];
    float p1 = h * W_loca[HID + t];
    float p2 = h * W_loca[2 * HID + t];
    p0 = warp_sum(p0); p1 = warp_sum(p1); p2 = warp_sum(p2);
    if (lane == 0) { sred[0][w] = p0; sred[1][w] = p1; sred[2][w] = p2; }

    __half* xh = d_xrh + (size_t)row * KREL;
    xh[XR_HL + t] = __float2half(h);
    if (t < 3)  xh[XR_ZWL + t] = __float2half(zwhere_last[inrow * 3 + t]);
    if (t < 50) xh[XR_ZWHATL + t] = __float2half(zwhat_last[inrow * 50 + t]);
    __syncthreads();
    if (t < 3) {
        float s = 0.0f;
#pragma unroll
        for (int q = 0; q < 8; q++) s += sred[t][q];
        s += b_loca[t];
        szw[t] = fmaxf(s, 0.0f) + zwhere_last[inrow * 3 + t];
    }
    __syncthreads();
    glimpse_hi(img + (size_t)n * IMG_HW, szw[0], szw[1], szw[2],
               d_G1h + (size_t)row * KENC, t);
}

// ---------------- HMMA fp16 single-term GEMM, fused epilogues ----------------
// CTA 128x128 (MxN), BK=32, 4-stage cp.async, 2 CTAs/SM.
// Warp tile 64x32 (2x4 warp grid, mf=4, nf=4). A single fp16; B single fp16.
// smem rows stride 80B (gcd(5,8)=1 -> ldmatrix conflict-free).
// Stage: A(128r) | B(128r) = 256 rows * 80B = 20480B
// EPI 0: rel LSTM pointwise (write d_cr, d_hr)
// EPI 1: relu -> fp16 out (enc)
// EPI 2: tem LSTM pointwise (read d_cr, write htemp_out)
#define ROW_B 80
#define OFF_B  (128 * ROW_B)         // 10240
#define STAGE_B (256 * ROW_B)        // 20480
#define SMEM_REQ (4 * STAGE_B)       // 81920

template <int EPI>
__global__ __launch_bounds__(256, 2) void hmma_gemm(
    const __half* __restrict__ A, int lda,
    const __half* __restrict__ B, int ldb,
    const float* __restrict__ bias,
    float* __restrict__ cstate, float* __restrict__ hout,
    __half* __restrict__ Chi, int ldc, int K, int nReal, int kk) {
    extern __shared__ char smem[];
    const uint32_t sb = smem_u32(smem);
    const int tid = threadIdx.x;
    const int lane = tid & 31, wid = tid >> 5;
    const int wm = wid >> 2, wn = wid & 3;      // 2 x 4 warp grid; warp tile 64x32
    const int bm = blockIdx.y * 128, bn = blockIdx.x * 128;
    const int nK = K / 32;

    float acc[4][4][4];
#pragma unroll
    for (int i = 0; i < 4; i++)
#pragma unroll
        for (int j = 0; j < 4; j++)
#pragma unroll
            for (int q = 0; q < 4; q++) acc[i][j][q] = 0.0f;

    auto load_stage = [&](int st, int kt) {
        int k0 = kt * 32;
        uint32_t base = sb + st * STAGE_B;
        // 256 rows * 4 chunks of 16B = 1024 cp.async ops; 256 threads -> 4 each
#pragma unroll
        for (int q = 0; q < 4; q++) {
            int idx = q * 256 + tid;          // 0..1023
            int row = idx >> 2;               // 0..255
            int ch = idx & 3;                 // 0..3
            const __half* gp;
            if (row < 128) gp = A + (size_t)(bm + row) * lda + k0 + ch * 8;
            else           gp = B + (size_t)(bn + row - 128) * ldb + k0 + ch * 8;
            cp16(base + row * ROW_B + ch * 16, gp);
        }
        cp_commit();
    };

    load_stage(0, 0);
    if (nK > 1) load_stage(1, 1);
    if (nK > 2) load_stage(2, 2);
    int st = 0;
    for (int kt = 0; kt < nK; kt++) {
        if (kt + 3 < nK) { load_stage((kt + 3) & 3, kt + 3); cp_wait3(); }
        else if (kt + 2 < nK) cp_wait2();
        else if (kt + 1 < nK) cp_wait1();
        else cp_wait0();
        __syncthreads();
        uint32_t base = sb + st * STAGE_B;
        st = (st + 1) & 3;
#pragma unroll
        for (int ks = 0; ks < 2; ks++) {
            uint32_t ar[4][4], br[4][2];
#pragma unroll
            for (int mf = 0; mf < 4; mf++) {
                int row = wm * 64 + mf * 16 + (lane & 15);
                int ch = ks * 2 + (lane >> 4);
                ldm_x4(ar[mf], base + row * ROW_B + ch * 16);
            }
#pragma unroll
            for (int nf = 0; nf < 4; nf++) {
                int row = wn * 32 + nf * 8 + (lane & 7);
                int ch = ks * 2 + ((lane >> 3) & 1);
                ldm_x2(br[nf], base + OFF_B + row * ROW_B + ch * 16);
            }
#pragma unroll
            for (int mf = 0; mf < 4; mf++)
#pragma unroll
                for (int nf = 0; nf < 4; nf++)
                    mma_f16(acc[mf][nf], ar[mf], br[nf]);
        }
        __syncthreads();
    }

    // epilogue
    int trow = lane >> 2, tcol2 = (lane & 3) * 2;
    bool evn = ((lane & 1) == 0);   // holds (i,f); odd holds (g,o)
#pragma unroll
    for (int mf = 0; mf < 4; mf++) {
        int r0 = bm + wm * 64 + mf * 16 + trow;
#pragma unroll
        for (int nf = 0; nf < 4; nf++) {
            int col = bn + wn * 32 + nf * 8 + tcol2;
            if (EPI == 1) {
#pragma unroll
                for (int e = 0; e < 4; e++) {
                    int cc = col + (e & 1);
                    int rr = r0 + (e >> 1) * 8;
                    if (cc < nReal) {
                        float v = fmaxf(acc[mf][nf][e] + bias[cc], 0.0f);
                        Chi[(size_t)rr * ldc + cc] = __float2half(v);
                    }
                }
            } else {
                int u = col >> 2;  // hidden unit
                float b0 = bias[col], b1 = bias[col + 1];
                float x0 = acc[mf][nf][0] + b0, x1 = acc[mf][nf][1] + b1;
                float x2 = acc[mf][nf][2] + b0, x3 = acc[mf][nf][3] + b1;
                float vA0, vB0, vA1, vB1;
                if (evn) { vA0 = sigm(x0); vB0 = sigm(x1); vA1 = sigm(x2); vB1 = sigm(x3); }
                else     { vA0 = tanhf(x0); vB0 = sigm(x1); vA1 = tanhf(x2); vB1 = sigm(x3); }
                // exchange: even receives tanh(g); odd receives sigm(i) (unused)
                float tA0 = __shfl_xor_sync(0xffffffffu, vA0, 1);
                float tA1 = __shfl_xor_sync(0xffffffffu, vA1, 1);
                float c20 = 0.0f, c21 = 0.0f;
                if (evn) {
                    float co0 = cstate[(size_t)r0 * HID + u];
                    float co1 = cstate[(size_t)(r0 + 8) * HID + u];
                    c20 = vB0 * co0 + vA0 * tA0;
                    c21 = vB1 * co1 + vA1 * tA1;
                    if (EPI == 0) {
                        cstate[(size_t)r0 * HID + u] = c20;
                        cstate[(size_t)(r0 + 8) * HID + u] = c21;
                    }
                }
                float cr0 = __shfl_xor_sync(0xffffffffu, c20, 1);
                float cr1 = __shfl_xor_sync(0xffffffffu, c21, 1);
                if (!evn) {
                    float h0 = vB0 * tanhf(cr0);
                    float h1 = vB1 * tanhf(cr1);
                    if (EPI == 0) {
                        hout[(size_t)r0 * HID + u] = h0;
                        hout[(size_t)(r0 + 8) * HID + u] = h1;
                    } else {   // EPI == 2: write h_t to output [n, k, HID]
                        hout[((size_t)r0 * KS + kk) * HID + u] = h0;
                        hout[((size_t)(r0 + 8) * KS + kk) * HID + u] = h1;
                    }
                }
            }
        }
    }
}

// ---------------- rel stage 2: zw linear + glimpse2 + xtem pack ----------------
__global__ __launch_bounds__(256) void relglimpse2_kernel(
    const float* __restrict__ img, const float* __restrict__ hidden_last,
    const float* __restrict__ zwhere_last, const float* __restrict__ zwhat_last,
    const float* __restrict__ Wm_wh, const float* __restrict__ bm_wh,
    const float* __restrict__ zwhat_out, float* __restrict__ zwhere_out, int k) {
    int n = blockIdx.x, t = threadIdx.x;
    __shared__ float hs[HID];
    __shared__ float sred[3][8];
    __shared__ float szw[3];
    int w = t >> 5, lane = t & 31;

    float h = d_hr[n * HID + t];    // h_r2 from rel GEMM epilogue
    hs[t] = h;

    __half* xh = d_xth + (size_t)n * KTEM;
    xh[XT_HR + t] = __float2half(h);
    xh[XT_HL + t] = __float2half(hidden_last[((size_t)n * KS + k) * HID + t]);
    if (t < 3) xh[XT_PZW + t] = __float2half(k ? zwhere_out[((size_t)n * KS + k - 1) * 3 + t] : 0.0f);
    if (t < 50) {
        xh[XT_ZWHATL + t] = __float2half(zwhat_last[((size_t)n * KS + k) * 50 + t]);
        xh[XT_PZWHAT + t] = __float2half(k ? zwhat_out[((size_t)n * KS + k - 1) * 50 + t] : 0.0f);
    }
    __syncthreads();

    // zw = [zwl(3), h_r2(256)] @ Wm_wh^T + bm_wh (K=259)
    float c0 = (t < 3) ? zwhere_last[((size_t)n * KS + k) * 3 + t] : hs[t - 3];
    float q0 = c0 * Wm_wh[t];
    float q1 = c0 * Wm_wh[259 + t];
    float q2 = c0 * Wm_wh[518 + t];
    if (t < 3) {
        float c1 = hs[253 + t];
        q0 += c1 * Wm_wh[256 + t];
        q1 += c1 * Wm_wh[259 + 256 + t];
        q2 += c1 * Wm_wh[518 + 256 + t];
    }
    q0 = warp_sum(q0); q1 = warp_sum(q1); q2 = warp_sum(q2);
    if (lane == 0) { sred[0][w] = q0; sred[1][w] = q1; sred[2][w] = q2; }
    __syncthreads();
    if (t < 3) {
        float s = 0.0f;
#pragma unroll
        for (int q = 0; q < 8; q++) s += sred[t][q];
        s += bm_wh[t];
        szw[t] = s;
        zwhere_out[((size_t)n * KS + k) * 3 + t] = s;
        xh[XT_ZW + t] = __float2half(s);
    }
    __syncthreads();
    glimpse_hi(img + (size_t)n * IMG_HW, szw[0], szw[1], szw[2], xh, t);
}

// ---------------- head: zwhat GEMV + presence + fused recpack for step k+1 ----------------
__global__ __launch_bounds__(256) void head_kernel(
    const float* __restrict__ zwhat_last, const float* __restrict__ zpres_last,
    const float* __restrict__ Wm_wt, const float* __restrict__ bm_wt,
    const float* __restrict__ Wm_pr, const float* __restrict__ bm_pr,
    const float* __restrict__ Ws_pr, const float* __restrict__ bs_pr,
    const float* __restrict__ zwhere_out, float* __restrict__ zwhat_out,
    float* __restrict__ zpres_out, const float* __restrict__ htemp_out, int k) {
    int n = blockIdx.x, t = threadIdx.x;
    __shared__ float xs[562];
    __shared__ float ys[565];
    __shared__ float red[16];
    int w = t >> 5, lane = t & 31;

    float ht = htemp_out[((size_t)n * KS + k) * HID + t];  // from tem GEMM epilogue
    float hr = d_hr[n * HID + t];
    xs[50 + t] = hr; xs[306 + t] = ht;
    ys[53 + t] = hr; ys[309 + t] = ht;
    if (t < 50) xs[t] = zwhat_last[((size_t)n * KS + k) * 50 + t];
    if (t < 3) ys[50 + t] = zwhere_out[((size_t)n * KS + k) * 3 + t];
    __syncthreads();

    for (int j = w; j < 50; j += 8) {
        const float* wr = Wm_wt + (size_t)j * 562;
        float acc = 0.0f;
        for (int i = lane; i < 562; i += 32) acc += xs[i] * wr[i];
        acc = warp_sum(acc);
        if (lane == 0) {
            float z = acc + bm_wt[j];
            ys[j] = z;
            zwhat_out[((size_t)n * KS + k) * 50 + j] = z;
        }
    }
    __syncthreads();

    // fused recpack for step k+1 (k-major xrel rows (k+1)*NB + n)
    if (k < KS - 1) {
        size_t row = (size_t)(k + 1) * NB + n;
        __half* xh = d_xrh + row * KREL;
        xh[XR_HR + t] = __float2half(hr);
        if (t < 3)  xh[XR_PZW + t] = __float2half(ys[50 + t]);
        if (t < 50) xh[XR_PZWHAT + t] = __float2half(ys[t]);
    }

    // presence: two 565-dots across the block
    float am = 0.0f, as = 0.0f;
    for (int i = t; i < 565; i += 256) {
        float x = ys[i];
        am += x * Wm_pr[i];
        as += x * Ws_pr[i];
    }
    am = warp_sum(am); as = warp_sum(as);
    if (lane == 0) { red[w] = am; red[8 + w] = as; }
    __syncthreads();
    if (t == 0) {
        float m = 0.0f, s = 0.0f;
#pragma unroll
        for (int q = 0; q < 8; q++) { m += red[q]; s += red[8 + q]; }
        float p = sigm(m + bm_pr[0]) * sigm(s + bs_pr[0]);
        zpres_out[(size_t)n * KS + k] = p * zpres_last[(size_t)n * KS + k];
    }
}

// ---------------- host ----------------
extern "C" void kernel_launch(void* const* d_in, const int* in_sizes, int n_in,
                              void* d_out, int out_size) {
    const float* img         = (const float*)d_in[0];
    const float* zwhat_last  = (const float*)d_in[1];
    const float* zwhere_last = (const float*)d_in[2];
    const float* zpres_last  = (const float*)d_in[3];
    const float* hidden_last = (const float*)d_in[4];
    const float* W_loca = (const float*)d_in[5];
    const float* b_loca = (const float*)d_in[6];
    const float* Wg     = (const float*)d_in[7];
    const float* bg     = (const float*)d_in[8];
    const float* Wih_rel = (const float*)d_in[9];
    const float* Whh_rel = (const float*)d_in[10];
    const float* bih_rel = (const float*)d_in[11];
    const float* bhh_rel = (const float*)d_in[12];
    const float* Wih_tem = (const float*)d_in[13];
    const float* Whh_tem = (const float*)d_in[14];
    const float* bih_tem = (const float*)d_in[15];
    const float* bhh_tem = (const float*)d_in[16];
    const float* Wm_wh = (const float*)d_in[17];
    const float* bm_wh = (const float*)d_in[18];
    const float* Wm_wt = (const float*)d_in[21];
    const float* bm_wt = (const float*)d_in[22];
    const float* Wm_pr = (const float*)d_in[25];
    const float* bm_pr = (const float*)d_in[26];
    const float* Ws_pr = (const float*)d_in[27];
    const float* bs_pr = (const float*)d_in[28];

    float* out = (float*)d_out;
    float* zwhat_out  = out;
    float* zwhere_out = out + (size_t)NB * KS * 50;
    float* zpres_out  = zwhere_out + (size_t)NB * KS * 3;
    float* htemp_out  = zpres_out + (size_t)NB * KS * 1;

    void *pG1h, *pXrh, *pXth;
    void *pWr, *pWt, *pWg, *pBrel, *pBtem, *pHr, *pCr;
    cudaGetSymbolAddress(&pG1h, d_G1h);
    cudaGetSymbolAddress(&pXrh, d_xrh);
    cudaGetSymbolAddress(&pXth, d_xth);
    cudaGetSymbolAddress(&pWr, d_Wr); cudaGetSymbolAddress(&pWt, d_Wt);
    cudaGetSymbolAddress(&pWg, d_Wg);
    cudaGetSymbolAddress(&pBrel, d_brel); cudaGetSymbolAddress(&pBtem, d_btem);
    cudaGetSymbolAddress(&pHr, d_hr); cudaGetSymbolAddress(&pCr, d_cr);

    cudaFuncSetAttribute(hmma_gemm<0>, cudaFuncAttributeMaxDynamicSharedMemorySize, SMEM_REQ);
    cudaFuncSetAttribute(hmma_gemm<1>, cudaFuncAttributeMaxDynamicSharedMemorySize, SMEM_REQ);
    cudaFuncSetAttribute(hmma_gemm<2>, cudaFuncAttributeMaxDynamicSharedMemorySize, SMEM_REQ);

    prep_kernel<<<2048, 256>>>(Wih_rel, Whh_rel, bih_rel, bhh_rel,
                               Wih_tem, Whh_tem, bih_tem, bhh_tem, Wg);
    staticpack_kernel<<<NB * KS, 256>>>(img, hidden_last, zwhere_last, zwhat_last,
                                        W_loca, b_loca);
    // enc GEMM: M=16384, N=128(100 real), K=2560
    {
        dim3 grid(1, NB * KS / 128);
        hmma_gemm<1><<<grid, 256, SMEM_REQ>>>(
            (const __half*)pG1h, KENC,
            (const __half*)pWg, KENC,
            bg, nullptr, nullptr,
            (__half*)pXrh, KREL, KENC, 100, 0);
    }
    for (int k = 0; k < KS; k++) {
        // rel gates GEMM + LSTM epilogue: M=2048 (k-major rows), N=1024, K=768
        {
            dim3 grid(NGATE / 128, NB / 128);
            hmma_gemm<0><<<grid, 256, SMEM_REQ>>>(
                (const __half*)pXrh + (size_t)k * NB * KREL, KREL,
                (const __half*)pWr, KREL,
                (const float*)pBrel, (float*)pCr, (float*)pHr,
                nullptr, 0, KREL, NGATE, k);
        }
        relglimpse2_kernel<<<NB, 256>>>(img, hidden_last, zwhere_last, zwhat_last,
                                        Wm_wh, bm_wh, zwhat_out, zwhere_out, k);
        // tem gates GEMM + LSTM epilogue: M=2048, N=1024, K=3136
        {
            dim3 grid(NGATE / 128, NB / 128);
            hmma_gemm<2><<<grid, 256, SMEM_REQ>>>(
                (const __half*)pXth, KTEM,
                (const __half*)pWt, KTEM,
                (const float*)pBtem, (float*)pCr, htemp_out,
                nullptr, 0, KTEM, NGATE, k);
        }
        head_kernel<<<NB, 256>>>(zwhat_last, zpres_last, Wm_wt, bm_wt,
                                 Wm_pr, bm_pr, Ws_pr, bs_pr,
                                 zwhere_out, zwhat_out, zpres_out, htemp_out, k);
    }
}

// round 15
// speedup vs baseline: 1.8669x; 1.0200x over previous
#include <cuda_runtime.h>
#include <cuda_fp16.h>
#include <cstdint>
#include <math.h>

#define NB   2048
#define KS   8
#define HID  256
#define IMG_HW 16384

#define KENC 2560   // glimpse K padded (2500 real)
#define KREL 768    // rel K padded (718 real)
#define KTEM 3136   // tem K padded (3118 real)
#define NGATE 1024

// xrel col offsets: [enc100|zwl3|pzw3|zwhatl50|pzwhat50|hl256|h_r256]
#define XR_ZWL 100
#define XR_PZW 103
#define XR_ZWHATL 106
#define XR_PZWHAT 156
#define XR_HL  206
#define XR_HR  462
// xtem col offsets: [g2 2500|zw3|pzw3|zwhatl50|pzwhat50|hl256|h_r2 256]
#define XT_ZW 2500
#define XT_PZW 2503
#define XT_ZWHATL 2506
#define XT_PZWHAT 2556
#define XT_HL 2606
#define XT_HR 2862

// ---------------- scratch ----------------
// fp16 activations, hi only (single-term GEMMs); k-major layout: row = k*NB + n
__device__ __half d_G1h[(size_t)NB * KS * KENC];
__device__ __half d_xrh[(size_t)NB * KS * KREL];
__device__ __half d_xth[(size_t)NB * KTEM];
__device__ __half d_imgh[(size_t)NB * IMG_HW];   // fp16 image copy (64MB, L2-resident)
__device__ float d_hr[(size_t)NB * HID];
__device__ float d_cr[(size_t)NB * HID];
// weights: single fp16, gate-interleaved rows (row' = unit*4 + gate)
__device__ __half d_Wr[(size_t)NGATE * KREL];
__device__ __half d_Wt[(size_t)NGATE * KTEM];
__device__ __half d_Wg[(size_t)128 * KENC];
__device__ float d_brel[NGATE];
__device__ float d_btem[NGATE];

// ---------------- ptx helpers (sm_80-era, safe for compute_103 PTX) ----------------
__device__ __forceinline__ uint32_t smem_u32(const void* p) {
    uint32_t a;
    asm("{ .reg .u64 t; cvta.to.shared.u64 t, %1; cvt.u32.u64 %0, t; }" : "=r"(a) : "l"(p));
    return a;
}
__device__ __forceinline__ void cp16(uint32_t dst, const void* src) {
    asm volatile("cp.async.ca.shared.global [%0], [%1], 16;" :: "r"(dst), "l"(src));
}
__device__ __forceinline__ void cp_commit() { asm volatile("cp.async.commit_group;"); }
__device__ __forceinline__ void cp_wait2() { asm volatile("cp.async.wait_group 2;"); }
__device__ __forceinline__ void cp_wait1() { asm volatile("cp.async.wait_group 1;"); }
__device__ __forceinline__ void cp_wait0() { asm volatile("cp.async.wait_group 0;"); }
__device__ __forceinline__ void ldm_x4(uint32_t* r, uint32_t a) {
    asm volatile("ldmatrix.sync.aligned.m8n8.x4.shared.b16 {%0,%1,%2,%3}, [%4];"
                 : "=r"(r[0]), "=r"(r[1]), "=r"(r[2]), "=r"(r[3]) : "r"(a));
}
__device__ __forceinline__ void ldm_x2(uint32_t* r, uint32_t a) {
    asm volatile("ldmatrix.sync.aligned.m8n8.x2.shared.b16 {%0,%1}, [%2];"
                 : "=r"(r[0]), "=r"(r[1]) : "r"(a));
}
__device__ __forceinline__ void mma_f16(float* c, const uint32_t* a, const uint32_t* b) {
    asm volatile("mma.sync.aligned.m16n8k16.row.col.f32.f16.f16.f32 "
                 "{%0,%1,%2,%3}, {%4,%5,%6,%7}, {%8,%9}, {%0,%1,%2,%3};"
                 : "+f"(c[0]), "+f"(c[1]), "+f"(c[2]), "+f"(c[3])
                 : "r"(a[0]), "r"(a[1]), "r"(a[2]), "r"(a[3]), "r"(b[0]), "r"(b[1]));
}

// ---------------- math helpers ----------------
// fast sigmoid: safe at extremes (inf handled by __fdividef -> 0/1)
__device__ __forceinline__ float sigm(float x) {
    return __fdividef(1.0f, 1.0f + __expf(-x));
}
// fast tanh: clamp to avoid inf/inf
__device__ __forceinline__ float ftanh(float x) {
    x = fminf(fmaxf(x, -9.0f), 9.0f);
    float e = __expf(2.0f * x);
    return __fdividef(e - 1.0f, e + 1.0f);
}
__device__ __forceinline__ float warp_sum(float v) {
#pragma unroll
    for (int o = 16; o; o >>= 1) v += __shfl_xor_sync(0xffffffffu, v, o);
    return v;
}
__device__ __forceinline__ float samp(const __half* __restrict__ im, int y, int x) {
    if ((unsigned)y < 128u && (unsigned)x < 128u) return __half2float(im[(y << 7) + x]);
    return 0.0f;
}
__device__ __forceinline__ float bilin(const __half* __restrict__ imgN,
                                       float s, float tx, float ty, int g) {
    int iy = g / 50, ix = g - iy * 50;
    float gx = -1.0f + (float)ix * (2.0f / 49.0f);
    float gy = -1.0f + (float)iy * (2.0f / 49.0f);
    float px = (s * gx + tx + 1.0f) * 0.5f * 127.0f;
    float py = (s * gy + ty + 1.0f) * 0.5f * 127.0f;
    float x0f = floorf(px), y0f = floorf(py);
    float wx1 = px - x0f, wy1 = py - y0f;
    int x0 = (int)x0f, y0 = (int)y0f;
    float v00 = samp(imgN, y0, x0),     v01 = samp(imgN, y0, x0 + 1);
    float v10 = samp(imgN, y0 + 1, x0), v11 = samp(imgN, y0 + 1, x0 + 1);
    return (1.0f - wy1) * (1.0f - wx1) * v00 + (1.0f - wy1) * wx1 * v01
         + wy1 * (1.0f - wx1) * v10 + wy1 * wx1 * v11;
}
__device__ __forceinline__ void glimpse_hi(const __half* __restrict__ imgN,
                                           float s, float tx, float ty,
                                           __half* __restrict__ dh, int t) {
    for (int g = t; g < 2500; g += 256) {
        dh[g] = __float2half(bilin(imgN, s, tx, ty, g));
    }
}

// ---------------- prep ----------------
__global__ void prep_kernel(const float* __restrict__ Wih_rel, const float* __restrict__ Whh_rel,
                            const float* __restrict__ bih_rel, const float* __restrict__ bhh_rel,
                            const float* __restrict__ Wih_tem, const float* __restrict__ Whh_tem,
                            const float* __restrict__ bih_tem, const float* __restrict__ bhh_tem,
                            const float* __restrict__ Wg, const float* __restrict__ img) {
    int tid = blockIdx.x * blockDim.x + threadIdx.x;
    int nt = gridDim.x * blockDim.x;
    // fp16 image copy
    for (size_t i = tid; i < (size_t)NB * IMG_HW; i += nt)
        d_imgh[i] = __float2half(img[i]);
    // gate-interleaved: out row r' -> unit u=r'>>2, gate g=r'&3, orig row = g*256+u
    for (int i = tid; i < NGATE * KREL; i += nt) {
        int rp = i / KREL, c = i - rp * KREL;
        int orig = (rp & 3) * 256 + (rp >> 2);
        float v = 0.0f;
        if (c < 462) v = Wih_rel[orig * 462 + c];
        else if (c < 718) v = Whh_rel[orig * 256 + (c - 462)];
        d_Wr[i] = __float2half(v);
    }
    for (int i = tid; i < NGATE * KTEM; i += nt) {
        int rp = i / KTEM, c = i - rp * KTEM;
        int orig = (rp & 3) * 256 + (rp >> 2);
        float v = 0.0f;
        if (c < 2862) v = Wih_tem[orig * 2862 + c];
        else if (c < 3118) v = Whh_tem[orig * 256 + (c - 2862)];
        d_Wt[i] = __float2half(v);
    }
    for (int i = tid; i < 128 * KENC; i += nt) {
        int r = i / KENC, c = i - r * KENC;
        float v = (r < 100 && c < 2500) ? Wg[r * 2500 + c] : 0.0f;
        d_Wg[i] = __float2half(v);
    }
    for (int i = tid; i < NGATE; i += nt) {
        int orig = (i & 3) * 256 + (i >> 2);
        d_brel[i] = bih_rel[orig] + bhh_rel[orig];
        d_btem[i] = bih_tem[orig] + bhh_tem[orig];
    }
    for (int i = tid; i < NB * HID; i += nt) { d_hr[i] = 0.0f; d_cr[i] = 0.0f; }
    __half z = __float2half(0.0f);
    // zero recurrent xrel cols for k=0 rows
    for (int i = tid; i < NB * 3; i += nt) {
        int r = i / 3, c = XR_PZW + i % 3;
        d_xrh[(size_t)r * KREL + c] = z;
    }
    for (int i = tid; i < NB * 50; i += nt) {
        int r = i / 50, c = XR_PZWHAT + i % 50;
        d_xrh[(size_t)r * KREL + c] = z;
    }
    for (int i = tid; i < NB * HID; i += nt) {
        int r = i / HID, c = XR_HR + i % HID;
        d_xrh[(size_t)r * KREL + c] = z;
    }
    // pads
    for (int i = tid; i < NB * KS * 60; i += nt) {
        int r = i / 60, c = 2500 + i % 60;
        d_G1h[(size_t)r * KENC + c] = z;
    }
    for (int i = tid; i < NB * KS * 50; i += nt) {
        int r = i / 50, c = 718 + i % 50;
        d_xrh[(size_t)r * KREL + c] = z;
    }
    for (int i = tid; i < NB * 18; i += nt) {
        int r = i / 18, c = 3118 + i % 18;
        d_xth[(size_t)r * KTEM + c] = z;
    }
}

// ---------------- static pack: zwb + glimpse1 + static xrel cols, all (n,k) ----------------
__global__ __launch_bounds__(256) void staticpack_kernel(
    const float* __restrict__ hidden_last,
    const float* __restrict__ zwhere_last, const float* __restrict__ zwhat_last,
    const float* __restrict__ W_loca, const float* __restrict__ b_loca) {
    int row = blockIdx.x, t = threadIdx.x;   // row = k*NB + n
    int k = row / NB, n = row - k * NB;
    size_t inrow = (size_t)n * KS + k;
    __shared__ float sred[3][8];
    __shared__ float szw[3];
    int w = t >> 5, lane = t & 31;

    float h = hidden_last[inrow * HID + t];
    float p0 = h * W_loca[t];
    float p1 = h * W_loca[HID + t];
    float p2 = h * W_loca[2 * HID + t];
    p0 = warp_sum(p0); p1 = warp_sum(p1); p2 = warp_sum(p2);
    if (lane == 0) { sred[0][w] = p0; sred[1][w] = p1; sred[2][w] = p2; }

    __half* xh = d_xrh + (size_t)row * KREL;
    xh[XR_HL + t] = __float2half(h);
    if (t < 3)  xh[XR_ZWL + t] = __float2half(zwhere_last[inrow * 3 + t]);
    if (t < 50) xh[XR_ZWHATL + t] = __float2half(zwhat_last[inrow * 50 + t]);
    __syncthreads();
    if (t < 3) {
        float s = 0.0f;
#pragma unroll
        for (int q = 0; q < 8; q++) s += sred[t][q];
        s += b_loca[t];
        szw[t] = fmaxf(s, 0.0f) + zwhere_last[inrow * 3 + t];
    }
    __syncthreads();
    glimpse_hi(d_imgh + (size_t)n * IMG_HW, szw[0], szw[1], szw[2],
               d_G1h + (size_t)row * KENC, t);
}

// ---------------- HMMA fp16 single-term GEMM, fused epilogues ----------------
// CTA 128x128 (MxN), BK=32, 4-stage ring / prefetch distance 2, ONE sync per iter.
// Warp tile 64x32 (2x4 warp grid). smem rows stride 80B (gcd(5,8)=1, conflict-free).
// Stage: A(128r) | B(128r) = 256 rows * 80B = 20480B
// EPI 0: rel LSTM pointwise (write d_cr, d_hr)
// EPI 1: relu -> fp16 out (enc)
// EPI 2: tem LSTM pointwise (read d_cr, write htemp_out)
#define ROW_B 80
#define OFF_B  (128 * ROW_B)         // 10240
#define STAGE_B (256 * ROW_B)        // 20480
#define SMEM_REQ (4 * STAGE_B)       // 81920

template <int EPI>
__global__ __launch_bounds__(256, 2) void hmma_gemm(
    const __half* __restrict__ A, int lda,
    const __half* __restrict__ B, int ldb,
    const float* __restrict__ bias,
    float* __restrict__ cstate, float* __restrict__ hout,
    __half* __restrict__ Chi, int ldc, int K, int nReal, int kk) {
    extern __shared__ char smem[];
    const uint32_t sb = smem_u32(smem);
    const int tid = threadIdx.x;
    const int lane = tid & 31, wid = tid >> 5;
    const int wm = wid >> 2, wn = wid & 3;      // 2 x 4 warp grid; warp tile 64x32
    const int bm = blockIdx.y * 128, bn = blockIdx.x * 128;
    const int nK = K / 32;

    float acc[4][4][4];
#pragma unroll
    for (int i = 0; i < 4; i++)
#pragma unroll
        for (int j = 0; j < 4; j++)
#pragma unroll
            for (int q = 0; q < 4; q++) acc[i][j][q] = 0.0f;

    auto load_stage = [&](int st, int kt) {
        int k0 = kt * 32;
        uint32_t base = sb + st * STAGE_B;
#pragma unroll
        for (int q = 0; q < 4; q++) {
            int idx = q * 256 + tid;          // 0..1023
            int row = idx >> 2;               // 0..255
            int ch = idx & 3;                 // 0..3
            const __half* gp;
            if (row < 128) gp = A + (size_t)(bm + row) * lda + k0 + ch * 8;
            else           gp = B + (size_t)(bn + row - 128) * ldb + k0 + ch * 8;
            cp16(base + row * ROW_B + ch * 16, gp);
        }
        cp_commit();
    };

    // prefetch distance 2: stages kt, kt+1, kt+2 live; 4-stage ring gives the
    // slack that makes a single per-iter barrier safe (overwrite target was
    // last consumed two barriers ago).
    load_stage(0, 0);
    if (nK > 1) load_stage(1, 1);
    for (int kt = 0; kt < nK; kt++) {
        if (kt + 2 < nK) { load_stage((kt + 2) & 3, kt + 2); cp_wait2(); }
        else if (kt + 1 < nK) cp_wait1();
        else cp_wait0();
        __syncthreads();
        uint32_t base = sb + (kt & 3) * STAGE_B;
#pragma unroll
        for (int ks = 0; ks < 2; ks++) {
            uint32_t ar[4][4], br[4][2];
#pragma unroll
            for (int mf = 0; mf < 4; mf++) {
                int row = wm * 64 + mf * 16 + (lane & 15);
                int ch = ks * 2 + (lane >> 4);
                ldm_x4(ar[mf], base + row * ROW_B + ch * 16);
            }
#pragma unroll
            for (int nf = 0; nf < 4; nf++) {
                int row = wn * 32 + nf * 8 + (lane & 7);
                int ch = ks * 2 + ((lane >> 3) & 1);
                ldm_x2(br[nf], base + OFF_B + row * ROW_B + ch * 16);
            }
#pragma unroll
            for (int mf = 0; mf < 4; mf++)
#pragma unroll
                for (int nf = 0; nf < 4; nf++)
                    mma_f16(acc[mf][nf], ar[mf], br[nf]);
        }
    }

    // epilogue
    int trow = lane >> 2, tcol2 = (lane & 3) * 2;
    bool evn = ((lane & 1) == 0);   // holds (i,f); odd holds (g,o)
#pragma unroll
    for (int mf = 0; mf < 4; mf++) {
        int r0 = bm + wm * 64 + mf * 16 + trow;
#pragma unroll
        for (int nf = 0; nf < 4; nf++) {
            int col = bn + wn * 32 + nf * 8 + tcol2;
            if (EPI == 1) {
#pragma unroll
                for (int e = 0; e < 4; e++) {
                    int cc = col + (e & 1);
                    int rr = r0 + (e >> 1) * 8;
                    if (cc < nReal) {
                        float v = fmaxf(acc[mf][nf][e] + bias[cc], 0.0f);
                        Chi[(size_t)rr * ldc + cc] = __float2half(v);
                    }
                }
            } else {
                int u = col >> 2;  // hidden unit
                float b0 = bias[col], b1 = bias[col + 1];
                float x0 = acc[mf][nf][0] + b0, x1 = acc[mf][nf][1] + b1;
                float x2 = acc[mf][nf][2] + b0, x3 = acc[mf][nf][3] + b1;
                float vA0, vB0, vA1, vB1;
                if (evn) { vA0 = sigm(x0); vB0 = sigm(x1); vA1 = sigm(x2); vB1 = sigm(x3); }
                else     { vA0 = ftanh(x0); vB0 = sigm(x1); vA1 = ftanh(x2); vB1 = sigm(x3); }
                // exchange: even receives tanh(g); odd receives sigm(i) (unused)
                float tA0 = __shfl_xor_sync(0xffffffffu, vA0, 1);
                float tA1 = __shfl_xor_sync(0xffffffffu, vA1, 1);
                float c20 = 0.0f, c21 = 0.0f;
                if (evn) {
                    float co0 = cstate[(size_t)r0 * HID + u];
                    float co1 = cstate[(size_t)(r0 + 8) * HID + u];
                    c20 = vB0 * co0 + vA0 * tA0;
                    c21 = vB1 * co1 + vA1 * tA1;
                    if (EPI == 0) {
                        cstate[(size_t)r0 * HID + u] = c20;
                        cstate[(size_t)(r0 + 8) * HID + u] = c21;
                    }
                }
                float cr0 = __shfl_xor_sync(0xffffffffu, c20, 1);
                float cr1 = __shfl_xor_sync(0xffffffffu, c21, 1);
                if (!evn) {
                    float h0 = vB0 * ftanh(cr0);
                    float h1 = vB1 * ftanh(cr1);
                    if (EPI == 0) {
                        hout[(size_t)r0 * HID + u] = h0;
                        hout[(size_t)(r0 + 8) * HID + u] = h1;
                    } else {   // EPI == 2: write h_t to output [n, k, HID]
                        hout[((size_t)r0 * KS + kk) * HID + u] = h0;
                        hout[((size_t)(r0 + 8) * KS + kk) * HID + u] = h1;
                    }
                }
            }
        }
    }
}

// ---------------- rel stage 2: zw linear + glimpse2 + xtem pack ----------------
__global__ __launch_bounds__(256) void relglimpse2_kernel(
    const float* __restrict__ hidden_last,
    const float* __restrict__ zwhere_last, const float* __restrict__ zwhat_last,
    const float* __restrict__ Wm_wh, const float* __restrict__ bm_wh,
    const float* __restrict__ zwhat_out, float* __restrict__ zwhere_out, int k) {
    int n = blockIdx.x, t = threadIdx.x;
    __shared__ float hs[HID];
    __shared__ float sred[3][8];
    __shared__ float szw[3];
    int w = t >> 5, lane = t & 31;

    float h = d_hr[n * HID + t];    // h_r2 from rel GEMM epilogue
    hs[t] = h;

    __half* xh = d_xth + (size_t)n * KTEM;
    xh[XT_HR + t] = __float2half(h);
    xh[XT_HL + t] = __float2half(hidden_last[((size_t)n * KS + k) * HID + t]);
    if (t < 3) xh[XT_PZW + t] = __float2half(k ? zwhere_out[((size_t)n * KS + k - 1) * 3 + t] : 0.0f);
    if (t < 50) {
        xh[XT_ZWHATL + t] = __float2half(zwhat_last[((size_t)n * KS + k) * 50 + t]);
        xh[XT_PZWHAT + t] = __float2half(k ? zwhat_out[((size_t)n * KS + k - 1) * 50 + t] : 0.0f);
    }
    __syncthreads();

    // zw = [zwl(3), h_r2(256)] @ Wm_wh^T + bm_wh (K=259)
    float c0 = (t < 3) ? zwhere_last[((size_t)n * KS + k) * 3 + t] : hs[t - 3];
    float q0 = c0 * Wm_wh[t];
    float q1 = c0 * Wm_wh[259 + t];
    float q2 = c0 * Wm_wh[518 + t];
    if (t < 3) {
        float c1 = hs[253 + t];
        q0 += c1 * Wm_wh[256 + t];
        q1 += c1 * Wm_wh[259 + 256 + t];
        q2 += c1 * Wm_wh[518 + 256 + t];
    }
    q0 = warp_sum(q0); q1 = warp_sum(q1); q2 = warp_sum(q2);
    if (lane == 0) { sred[0][w] = q0; sred[1][w] = q1; sred[2][w] = q2; }
    __syncthreads();
    if (t < 3) {
        float s = 0.0f;
#pragma unroll
        for (int q = 0; q < 8; q++) s += sred[t][q];
        s += bm_wh[t];
        szw[t] = s;
        zwhere_out[((size_t)n * KS + k) * 3 + t] = s;
        xh[XT_ZW + t] = __float2half(s);
    }
    __syncthreads();
    glimpse_hi(d_imgh + (size_t)n * IMG_HW, szw[0], szw[1], szw[2], xh, t);
}

// ---------------- head: zwhat GEMV + presence + fused recpack for step k+1 ----------------
__global__ __launch_bounds__(256) void head_kernel(
    const float* __restrict__ zwhat_last, const float* __restrict__ zpres_last,
    const float* __restrict__ Wm_wt, const float* __restrict__ bm_wt,
    const float* __restrict__ Wm_pr, const float* __restrict__ bm_pr,
    const float* __restrict__ Ws_pr, const float* __restrict__ bs_pr,
    const float* __restrict__ zwhere_out, float* __restrict__ zwhat_out,
    float* __restrict__ zpres_out, const float* __restrict__ htemp_out, int k) {
    int n = blockIdx.x, t = threadIdx.x;
    __shared__ float xs[562];
    __shared__ float ys[565];
    __shared__ float red[16];
    int w = t >> 5, lane = t & 31;

    float ht = htemp_out[((size_t)n * KS + k) * HID + t];  // from tem GEMM epilogue
    float hr = d_hr[n * HID + t];
    xs[50 + t] = hr; xs[306 + t] = ht;
    ys[53 + t] = hr; ys[309 + t] = ht;
    if (t < 50) xs[t] = zwhat_last[((size_t)n * KS + k) * 50 + t];
    if (t < 3) ys[50 + t] = zwhere_out[((size_t)n * KS + k) * 3 + t];
    __syncthreads();

    for (int j = w; j < 50; j += 8) {
        const float* wr = Wm_wt + (size_t)j * 562;
        float acc = 0.0f;
        for (int i = lane; i < 562; i += 32) acc += xs[i] * wr[i];
        acc = warp_sum(acc);
        if (lane == 0) {
            float z = acc + bm_wt[j];
            ys[j] = z;
            zwhat_out[((size_t)n * KS + k) * 50 + j] = z;
        }
    }
    __syncthreads();

    // fused recpack for step k+1 (k-major xrel rows (k+1)*NB + n)
    if (k < KS - 1) {
        size_t row = (size_t)(k + 1) * NB + n;
        __half* xh = d_xrh + row * KREL;
        xh[XR_HR + t] = __float2half(hr);
        if (t < 3)  xh[XR_PZW + t] = __float2half(ys[50 + t]);
        if (t < 50) xh[XR_PZWHAT + t] = __float2half(ys[t]);
    }

    // presence: two 565-dots across the block
    float am = 0.0f, as = 0.0f;
    for (int i = t; i < 565; i += 256) {
        float x = ys[i];
        am += x * Wm_pr[i];
        as += x * Ws_pr[i];
    }
    am = warp_sum(am); as = warp_sum(as);
    if (lane == 0) { red[w] = am; red[8 + w] = as; }
    __syncthreads();
    if (t == 0) {
        float m = 0.0f, s = 0.0f;
#pragma unroll
        for (int q = 0; q < 8; q++) { m += red[q]; s += red[8 + q]; }
        float p = sigm(m + bm_pr[0]) * sigm(s + bs_pr[0]);
        zpres_out[(size_t)n * KS + k] = p * zpres_last[(size_t)n * KS + k];
    }
}

// ---------------- host ----------------
extern "C" void kernel_launch(void* const* d_in, const int* in_sizes, int n_in,
                              void* d_out, int out_size) {
    const float* img         = (const float*)d_in[0];
    const float* zwhat_last  = (const float*)d_in[1];
    const float* zwhere_last = (const float*)d_in[2];
    const float* zpres_last  = (const float*)d_in[3];
    const float* hidden_last = (const float*)d_in[4];
    const float* W_loca = (const float*)d_in[5];
    const float* b_loca = (const float*)d_in[6];
    const float* Wg     = (const float*)d_in[7];
    const float* bg     = (const float*)d_in[8];
    const float* Wih_rel = (const float*)d_in[9];
    const float* Whh_rel = (const float*)d_in[10];
    const float* bih_rel = (const float*)d_in[11];
    const float* bhh_rel = (const float*)d_in[12];
    const float* Wih_tem = (const float*)d_in[13];
    const float* Whh_tem = (const float*)d_in[14];
    const float* bih_tem = (const float*)d_in[15];
    const float* bhh_tem = (const float*)d_in[16];
    const float* Wm_wh = (const float*)d_in[17];
    const float* bm_wh = (const float*)d_in[18];
    const float* Wm_wt = (const float*)d_in[21];
    const float* bm_wt = (const float*)d_in[22];
    const float* Wm_pr = (const float*)d_in[25];
    const float* bm_pr = (const float*)d_in[26];
    const float* Ws_pr = (const float*)d_in[27];
    const float* bs_pr = (const float*)d_in[28];

    float* out = (float*)d_out;
    float* zwhat_out  = out;
    float* zwhere_out = out + (size_t)NB * KS * 50;
    float* zpres_out  = zwhere_out + (size_t)NB * KS * 3;
    float* htemp_out  = zpres_out + (size_t)NB * KS * 1;

    void *pG1h, *pXrh, *pXth;
    void *pWr, *pWt, *pWg, *pBrel, *pBtem, *pHr, *pCr;
    cudaGetSymbolAddress(&pG1h, d_G1h);
    cudaGetSymbolAddress(&pXrh, d_xrh);
    cudaGetSymbolAddress(&pXth, d_xth);
    cudaGetSymbolAddress(&pWr, d_Wr); cudaGetSymbolAddress(&pWt, d_Wt);
    cudaGetSymbolAddress(&pWg, d_Wg);
    cudaGetSymbolAddress(&pBrel, d_brel); cudaGetSymbolAddress(&pBtem, d_btem);
    cudaGetSymbolAddress(&pHr, d_hr); cudaGetSymbolAddress(&pCr, d_cr);

    cudaFuncSetAttribute(hmma_gemm<0>, cudaFuncAttributeMaxDynamicSharedMemorySize, SMEM_REQ);
    cudaFuncSetAttribute(hmma_gemm<1>, cudaFuncAttributeMaxDynamicSharedMemorySize, SMEM_REQ);
    cudaFuncSetAttribute(hmma_gemm<2>, cudaFuncAttributeMaxDynamicSharedMemorySize, SMEM_REQ);

    prep_kernel<<<2048, 256>>>(Wih_rel, Whh_rel, bih_rel, bhh_rel,
                               Wih_tem, Whh_tem, bih_tem, bhh_tem, Wg, img);
    staticpack_kernel<<<NB * KS, 256>>>(hidden_last, zwhere_last, zwhat_last,
                                        W_loca, b_loca);
    // enc GEMM: M=16384, N=128(100 real), K=2560
    {
        dim3 grid(1, NB * KS / 128);
        hmma_gemm<1><<<grid, 256, SMEM_REQ>>>(
            (const __half*)pG1h, KENC,
            (const __half*)pWg, KENC,
            bg, nullptr, nullptr,
            (__half*)pXrh, KREL, KENC, 100, 0);
    }
    for (int k = 0; k < KS; k++) {
        // rel gates GEMM + LSTM epilogue: M=2048 (k-major rows), N=1024, K=768
        {
            dim3 grid(NGATE / 128, NB / 128);
            hmma_gemm<0><<<grid, 256, SMEM_REQ>>>(
                (const __half*)pXrh + (size_t)k * NB * KREL, KREL,
                (const __half*)pWr, KREL,
                (const float*)pBrel, (float*)pCr, (float*)pHr,
                nullptr, 0, KREL, NGATE, k);
        }
        relglimpse2_kernel<<<NB, 256>>>(hidden_last, zwhere_last, zwhat_last,
                                        Wm_wh, bm_wh, zwhat_out, zwhere_out, k);
        // tem gates GEMM + LSTM epilogue: M=2048, N=1024, K=3136
        {
            dim3 grid(NGATE / 128, NB / 128);
            hmma_gemm<2><<<grid, 256, SMEM_REQ>>>(
                (const __half*)pXth, KTEM,
                (const __half*)pWt, KTEM,
                (const float*)pBtem, (float*)pCr, htemp_out,
                nullptr, 0, KTEM, NGATE, k);
        }
        head_kernel<<<NB, 256>>>(zwhat_last, zpres_last, Wm_wt, bm_wt,
                                 Wm_pr, bm_pr, Ws_pr, bs_pr,
                                 zwhere_out, zwhat_out, zpres_out, htemp_out, k);
    }
}